// round 11
// baseline (speedup 1.0000x reference)
#include <cuda_runtime.h>
#include <cuda_fp16.h>
#include <cstdint>
#include <math.h>

#define B_   8
#define Q_   64
#define S_   64
#define T_   64
#define H_   8
#define DH_  64
#define NH_  512
#define NEGV (-1e6f)

// ---------------------------------------------------------------------------
// Scratch (device globals)
// ---------------------------------------------------------------------------
__device__ __half g_cq_h [512 * 512],  g_cq_l [512 * 512];    // queries hi/lo
__device__ __half g_csk_h[512 * 512],  g_csk_l[512 * 512];    // stat_keys hi/lo
__device__ __half g_wh[6 * 512 * 512], g_wl[6 * 512 * 512];   // W^T [N,K] fp16 hi/lo
__device__ float g_q_stat[512 * 512];
__device__ float g_q_tok [512 * 512];
__device__ float g_k_stat[512 * 512];
__device__ __half g_ktk16[8192 * 512];                        // projected token keys (fp16)
__device__ __half g_v16h [8192 * 512];                        // projected values (fp16)
__device__ __half g_at_h[512 * 512];                          // attn out fp16

// ---------------------------------------------------------------------------
// helpers
// ---------------------------------------------------------------------------
__device__ __forceinline__ uint32_t smem_u32(const void* p) {
    uint32_t a;
    asm("{ .reg .u64 t; cvta.to.shared.u64 t, %1; cvt.u32.u64 %0, t; }" : "=r"(a) : "l"(p));
    return a;
}
__device__ __forceinline__ void ldsm_x4(uint32_t* r, uint32_t addr) {
    asm volatile("ldmatrix.sync.aligned.m8n8.x4.shared.b16 {%0,%1,%2,%3}, [%4];"
        : "=r"(r[0]), "=r"(r[1]), "=r"(r[2]), "=r"(r[3]) : "r"(addr));
}
__device__ __forceinline__ void ldsm_x2(uint32_t* r, uint32_t addr) {
    asm volatile("ldmatrix.sync.aligned.m8n8.x2.shared.b16 {%0,%1}, [%2];"
        : "=r"(r[0]), "=r"(r[1]) : "r"(addr));
}
__device__ __forceinline__ void mma16816(float* d, const uint32_t* a, const uint32_t* b) {
    asm volatile("mma.sync.aligned.m16n8k16.row.col.f32.f16.f16.f32 "
        "{%0,%1,%2,%3}, {%4,%5,%6,%7}, {%8,%9}, {%0,%1,%2,%3};"
        : "+f"(d[0]), "+f"(d[1]), "+f"(d[2]), "+f"(d[3])
        : "r"(a[0]), "r"(a[1]), "r"(a[2]), "r"(a[3]), "r"(b[0]), "r"(b[1]));
}
__device__ __forceinline__ void cp16(uint32_t dst, const void* src) {
    asm volatile("cp.async.cg.shared.global [%0], [%1], 16;" :: "r"(dst), "l"(src));
}
#define CP_COMMIT() asm volatile("cp.async.commit_group;" ::: "memory")
#define CP_WAIT1()  asm volatile("cp.async.wait_group 1;" ::: "memory")
#define CP_WAIT0()  asm volatile("cp.async.wait_group 0;" ::: "memory")

__device__ __forceinline__ uint32_t pack2h(float a, float b) {
    return (uint32_t)__half_as_ushort(__float2half(a)) |
           ((uint32_t)__half_as_ushort(__float2half(b)) << 16);
}

// ---------------------------------------------------------------------------
// Convert q/sk -> fp16 hi/lo (small: 512 rows each)
// ---------------------------------------------------------------------------
__global__ __launch_bounds__(256)
void conv_act(const float* __restrict__ q, const float* __restrict__ sk) {
    const int z = blockIdx.y;
    const int idx = blockIdx.x * 256 + threadIdx.x;    // unit = 4 floats; 512*128 units
    const int r = idx >> 7, c4 = idx & 127;
    const float* src = z ? sk : q;
    __half* dh = z ? g_csk_h : g_cq_h;
    __half* dl = z ? g_csk_l : g_cq_l;
    float4 x = *(const float4*)&src[(size_t)r * 512 + c4 * 4];
    __half h0 = __float2half(x.x), h1 = __float2half(x.y),
           h2 = __float2half(x.z), h3 = __float2half(x.w);
    uint2 hh, ll;
    hh.x = (uint32_t)__half_as_ushort(h0) | ((uint32_t)__half_as_ushort(h1) << 16);
    hh.y = (uint32_t)__half_as_ushort(h2) | ((uint32_t)__half_as_ushort(h3) << 16);
    ll.x = pack2h(x.x - __half2float(h0), x.y - __half2float(h1));
    ll.y = pack2h(x.z - __half2float(h2), x.w - __half2float(h3));
    *(uint2*)&dh[(size_t)r * 512 + c4 * 4] = hh;
    *(uint2*)&dl[(size_t)r * 512 + c4 * 4] = ll;
}

// ---------------------------------------------------------------------------
// Weight prep: transpose W[K,N] fp32 -> Wt[N,K] fp16 hi/lo (6 weights)
// ---------------------------------------------------------------------------
struct WPtrs { const float* p[6]; };

__global__ __launch_bounds__(256)
void prep_w(WPtrs ws) {
    __shared__ float t[32][33];
    const int widx = blockIdx.z;
    const float* W = ws.p[widx];
    __half* hiw = g_wh + (size_t)widx * 512 * 512;
    __half* low = g_wl + (size_t)widx * 512 * 512;
    const int n0 = blockIdx.x * 32, k0 = blockIdx.y * 32;
    const int tx = threadIdx.x, ty = threadIdx.y;
#pragma unroll
    for (int i = ty; i < 32; i += 8)
        t[i][tx] = W[(size_t)(k0 + i) * 512 + n0 + tx];
    __syncthreads();
#pragma unroll
    for (int i = ty; i < 32; i += 8) {
        float v = t[tx][i];
        __half h = __float2half(v);
        hiw[(size_t)(n0 + i) * 512 + k0 + tx] = h;
        low[(size_t)(n0 + i) * 512 + k0 + tx] = __float2half(v - __half2float(h));
    }
}

// ---------------------------------------------------------------------------
// Batched fp16 hi/lo GEMM, cp.async 2-stage pipeline.
//   F[s] != nullptr : A is fp32 gathered source (last-16 token rows), register
//                     prefetch + in-kernel fp16 convert (2-term).
//   else Al != nullptr -> 3-term hi/lo A via cp.async, else 2-term.
//   Ho != nullptr -> fp16 output; else fp32 (C0/C1 split).
// ---------------------------------------------------------------------------
struct GemmBatch {
    const __half *Ah[4], *Al[4], *Bh[4], *Bl[4];
    const float *F[4];
    float *C0[4], *C1[4];
    __half *Ho[4];
    int nbx[4];
    int cnt[4];
};

__global__ __launch_bounds__(256)
void gemm_batched(GemmBatch args) {
    constexpr int MT = 4;
    constexpr uint32_t ABYTES = 128 * 80;
    constexpr uint32_t BBYTES = 128 * 80;
    constexpr uint32_t STG    = 2 * ABYTES + 2 * BBYTES;    // 40960
    extern __shared__ char smem[];
    const uint32_t sb = smem_u32(smem);

    int id = blockIdx.x, s = 0;
#pragma unroll
    for (int i = 0; i < 3; i++) {
        bool adv = (id >= args.cnt[s]);
        if (adv) { id -= args.cnt[s]; s++; }
    }
    const __half* Ah = args.Ah[s];
    const __half* Al = args.Al[s];
    const __half* Bh = args.Bh[s];
    const __half* Bl = args.Bl[s];
    const float*  F  = args.F[s];
    float* C0 = args.C0[s];
    float* C1 = args.C1[s];
    __half* Ho = args.Ho[s];
    const int nbx = args.nbx[s];
    const int bx = id % nbx, by = id / nbx;
    const int m0 = by * 128, n0 = bx * 128;

    const int tid = threadIdx.x;
    const int wid = tid >> 5, lane = tid & 31;
    const int wm = wid >> 2, wn = wid & 3;

    const uint32_t rowA = (uint32_t)(wm * 64 + (lane & 7) + ((lane >> 3) & 1) * 8);
    const uint32_t colA = (uint32_t)(((lane >> 4) & 1) * 16);
    const uint32_t oAh = rowA * 80 + colA;
    const uint32_t oAl = oAh + ABYTES;
    const uint32_t rowB = (uint32_t)(wn * 32 + (lane & 7));
    const uint32_t colB = (uint32_t)(((lane >> 3) & 1) * 16);
    const uint32_t oBh = 2 * ABYTES + rowB * 80 + colB;
    const uint32_t oBl = oBh + BBYTES;

    float acc[MT][4][4];
#pragma unroll
    for (int i = 0; i < MT; i++)
#pragma unroll
        for (int j = 0; j < 4; j++)
#pragma unroll
            for (int e = 0; e < 4; e++) acc[i][j][e] = 0.f;

    // precomputed per-thread A addressing (two 16B fp16 chunks per thread)
    int aRow[2], aQ[2];
    const float* fSrc[2];
#pragma unroll
    for (int i = 0; i < 2; i++) {
        int c = tid + i * 256;
        aRow[i] = c >> 2; aQ[i] = c & 3;
        if (F) {
            int gr = m0 + aRow[i];
            fSrc[i] = F + (size_t)((gr >> 4) * 64 + 48 + (gr & 15)) * 512 + aQ[i] * 8;
        } else {
            fSrc[i] = nullptr;
        }
    }

    // ---- F-mode A: register load + convert + STS (generic-space offsets!) ----
    float4 rA[4];
    auto ldA = [&](int kc) {
        const int k0 = kc * 32;
#pragma unroll
        for (int i = 0; i < 2; i++) {
            rA[i * 2 + 0] = *(const float4*)(fSrc[i] + k0);
            rA[i * 2 + 1] = *(const float4*)(fSrc[i] + k0 + 4);
        }
    };
    auto stA = [&](int st) {
        const uint32_t off0 = (uint32_t)st * STG;     // offset from smem base (NOT sb!)
#pragma unroll
        for (int i = 0; i < 2; i++) {
            uint4 h;
            h.x = pack2h(rA[i * 2].x,     rA[i * 2].y);
            h.y = pack2h(rA[i * 2].z,     rA[i * 2].w);
            h.z = pack2h(rA[i * 2 + 1].x, rA[i * 2 + 1].y);
            h.w = pack2h(rA[i * 2 + 1].z, rA[i * 2 + 1].w);
            *(uint4*)(smem + off0 + aRow[i] * 80 + aQ[i] * 16) = h;
        }
    };

    auto load_stage = [&](int st, int kc) {
        const int k0 = kc * 32;
        const uint32_t base = sb + st * STG;          // shared-space addr for cp.async
#pragma unroll
        for (int i = 0; i < 2; i++) {
            uint32_t dstB = base + 2 * ABYTES + aRow[i] * 80 + aQ[i] * 16;
            const size_t gb = (size_t)(n0 + aRow[i]) * 512 + k0 + aQ[i] * 8;
            cp16(dstB, Bh + gb);
            cp16(dstB + BBYTES, Bl + gb);
            if (!F) {
                uint32_t dst = base + aRow[i] * 80 + aQ[i] * 16;
                const size_t ga = (size_t)(m0 + aRow[i]) * 512 + k0 + aQ[i] * 8;
                cp16(dst, Ah + ga);
                if (Al) cp16(dst + ABYTES, Al + ga);
            }
        }
    };

    // prologue
    if (F) { ldA(0); stA(0); }
    load_stage(0, 0); CP_COMMIT();
    if (F) { ldA(1); stA(1); }
    load_stage(1, 1); CP_COMMIT();

    for (int kc = 0; kc < 16; kc++) {
        if (kc < 15) { CP_WAIT1(); } else { CP_WAIT0(); }
        __syncthreads();
        if (F && kc + 2 < 16) ldA(kc + 2);          // LDG overlaps MMAs below
        const uint32_t so = sb + (kc & 1) * STG;
#pragma unroll
        for (int ks = 0; ks < 2; ks++) {
            uint32_t bh[4][2], bl[4][2];
#pragma unroll
            for (int ni = 0; ni < 4; ni++) ldsm_x2(bh[ni], so + oBh + ni * 640 + ks * 32);
#pragma unroll
            for (int ni = 0; ni < 4; ni++) ldsm_x2(bl[ni], so + oBl + ni * 640 + ks * 32);
#pragma unroll
            for (int mi = 0; mi < MT; mi++) {
                uint32_t ah[4];
                ldsm_x4(ah, so + oAh + mi * 1280 + ks * 32);
#pragma unroll
                for (int ni = 0; ni < 4; ni++) mma16816(acc[mi][ni], ah, bh[ni]);
#pragma unroll
                for (int ni = 0; ni < 4; ni++) mma16816(acc[mi][ni], ah, bl[ni]);
                if (Al) {
                    uint32_t al[4];
                    ldsm_x4(al, so + oAl + mi * 1280 + ks * 32);
#pragma unroll
                    for (int ni = 0; ni < 4; ni++) mma16816(acc[mi][ni], al, bh[ni]);
                }
            }
        }
        __syncthreads();
        if (kc + 2 < 16) {
            if (F) stA(kc & 1);
            load_stage(kc & 1, kc + 2);
        }
        CP_COMMIT();
    }

    const int mrow = m0 + wm * 64 + (lane >> 2);
    const int ncol = n0 + wn * 32 + (lane & 3) * 2;
#pragma unroll
    for (int mi = 0; mi < MT; mi++) {
#pragma unroll
        for (int ni = 0; ni < 4; ni++) {
            int col = ncol + ni * 8;
            int r0 = mrow + mi * 16;
            if (Ho) {
                *(__half2*)&Ho[(size_t)r0 * 512 + col] =
                    __floats2half2_rn(acc[mi][ni][0], acc[mi][ni][1]);
                *(__half2*)&Ho[(size_t)(r0 + 8) * 512 + col] =
                    __floats2half2_rn(acc[mi][ni][2], acc[mi][ni][3]);
            } else {
                float* dst = (C1 && col >= 512) ? (C1 + col - 512) : (C0 + col);
                *(float2*)&dst[(size_t)r0 * 512]       = make_float2(acc[mi][ni][0], acc[mi][ni][1]);
                *(float2*)&dst[(size_t)(r0 + 8) * 512] = make_float2(acc[mi][ni][2], acc[mi][ni][3]);
            }
        }
    }
}

// ---------------------------------------------------------------------------
// Hierarchical attention v2 (round 9, passing): block per (b,h,q-half).
// ---------------------------------------------------------------------------
#define ATTN_SMEM 195584

__global__ __launch_bounds__(512)
void attn2(const int* __restrict__ valid_lens) {
    extern __shared__ char sm[];
    __half* kv   = (__half*)sm;                                 // [1024][66]
    float*  ks_t = (float*)(sm + 135168);                       // [64][68]
    float*  qs   = (float*)(sm + 135168 + 17408);               // [32][64]
    float*  qt   = qs + 2048;
    float*  sc   = qt + 2048;
    float*  cw   = sc + 2048;                                   // [32][128]
    int*    sidx = (int*)(cw + 4096);                           // [32][8]
    float*  sw8  = (float*)(sidx + 256);                        // [32][8]

    const int bh = blockIdx.x;
    const int b = bh >> 3, h = bh & 7;
    const int qh = blockIdx.y;
    const int qbase = b * 64 + qh * 32;
    const int tid = threadIdx.x, wid = tid >> 5, lane = tid & 31;
    const float scale = 0.125f;

#pragma unroll
    for (int k = 0; k < 2; k++) {
        int i4 = tid + k * 512;
        int s = i4 >> 4, dq = i4 & 15;
        float4 v = *(const float4*)&g_k_stat[(size_t)(b * 64 + s) * 512 + h * 64 + dq * 4];
        ks_t[(dq * 4 + 0) * 68 + s] = v.x;
        ks_t[(dq * 4 + 1) * 68 + s] = v.y;
        ks_t[(dq * 4 + 2) * 68 + s] = v.z;
        ks_t[(dq * 4 + 3) * 68 + s] = v.w;
    }
    {
        int q = tid >> 4, dq = tid & 15;
        *(float4*)&qs[q * 64 + dq * 4] =
            *(const float4*)&g_q_stat[(size_t)(qbase + q) * 512 + h * 64 + dq * 4];
        *(float4*)&qt[q * 64 + dq * 4] =
            *(const float4*)&g_q_tok[(size_t)(qbase + q) * 512 + h * 64 + dq * 4];
    }
#pragma unroll
    for (int k = 0; k < 16; k++) {
        int idx = tid + k * 512;
        int r = idx >> 3, c = idx & 7;
        uint4 v = *(const uint4*)&g_ktk16[((size_t)(b * 1024) + r) * 512 + h * 64 + c * 8];
        uint32_t* dst = (uint32_t*)kv + r * 33 + c * 4;
        dst[0] = v.x; dst[1] = v.y; dst[2] = v.z; dst[3] = v.w;
    }
    __syncthreads();

    const int vlen = valid_lens[b];

    {
        const int q = tid >> 4, sg = tid & 15;
        float a0 = 0.f, a1 = 0.f, a2 = 0.f, a3 = 0.f;
        const float* qrow = &qs[q * 64];
#pragma unroll
        for (int d = 0; d < 64; d++) {
            float qv = qrow[d];
            float4 kf = *(const float4*)&ks_t[d * 68 + sg * 4];
            a0 = fmaf(qv, kf.x, a0);
            a1 = fmaf(qv, kf.y, a1);
            a2 = fmaf(qv, kf.z, a2);
            a3 = fmaf(qv, kf.w, a3);
        }
        const int s0 = sg * 4;
        sc[q * 64 + s0 + 0] = (s0 + 0 < vlen) ? a0 * scale : NEGV;
        sc[q * 64 + s0 + 1] = (s0 + 1 < vlen) ? a1 * scale : NEGV;
        sc[q * 64 + s0 + 2] = (s0 + 2 < vlen) ? a2 * scale : NEGV;
        sc[q * 64 + s0 + 3] = (s0 + 3 < vlen) ? a3 * scale : NEGV;
    }
    __syncthreads();

    for (int rep = 0; rep < 2; rep++) {
        const int q = wid * 2 + rep;
        float v0 = sc[q * 64 + lane], v1 = sc[q * 64 + lane + 32];
        int i0 = lane, i1 = lane + 32;
        float vals[8];
#pragma unroll
        for (int j = 0; j < 8; j++) {
            float m; int mi;
            if (v0 >= v1) { m = v0; mi = i0; } else { m = v1; mi = i1; }
#pragma unroll
            for (int o = 16; o; o >>= 1) {
                float om = __shfl_xor_sync(~0u, m, o);
                int   oi = __shfl_xor_sync(~0u, mi, o);
                if (om > m || (om == m && oi < mi)) { m = om; mi = oi; }
            }
            if (lane == 0) { sidx[q * 8 + j] = mi; vals[j] = m; }
            if (i0 == mi) v0 = -3.0e38f;
            if (i1 == mi) v1 = -3.0e38f;
        }
        if (lane == 0) {
            const float m = vals[0];
            float e[8], sum = 0.f;
#pragma unroll
            for (int j = 0; j < 8; j++) { e[j] = expf(vals[j] - m); sum += e[j]; }
            const float inv = 1.f / sum;
#pragma unroll
            for (int j = 0; j < 8; j++) sw8[q * 8 + j] = e[j] * inv;
        }
    }
    __syncthreads();

    {
        const int t = lane >> 1, hf = lane & 1;
        for (int kk = 0; kk < 16; kk++) {
            const int q = wid * 2 + (kk >> 3);
            const int j = kk & 7;
            const int row = sidx[q * 8 + j] * 16 + t;
            const uint32_t* kr = (const uint32_t*)kv + row * 33 + hf * 16;
            const float* qr = &qt[q * 64 + hf * 32];
            float acc = 0.f;
#pragma unroll
            for (int it = 0; it < 16; it++) {
                float2 kf = __half22float2(*(const __half2*)&kr[it]);
                float2 q2 = *(const float2*)&qr[it * 2];
                acc = fmaf(q2.x, kf.x, acc);
                acc = fmaf(q2.y, kf.y, acc);
            }
            acc += __shfl_xor_sync(~0u, acc, 1);
            if (hf == 0) cw[q * 128 + j * 16 + t] = acc * scale;
        }
    }
    __syncthreads();

#pragma unroll
    for (int k = 0; k < 16; k++) {
        int idx = tid + k * 512;
        int r = idx >> 3, c = idx & 7;
        uint4 v = *(const uint4*)&g_v16h[((size_t)(b * 1024) + r) * 512 + h * 64 + c * 8];
        uint32_t* dst = (uint32_t*)kv + r * 33 + c * 4;
        dst[0] = v.x; dst[1] = v.y; dst[2] = v.z; dst[3] = v.w;
    }
    if (tid < 256) {
        const int q = tid >> 3, j = tid & 7;
        float* c = &cw[q * 128 + j * 16];
        float m = c[0];
#pragma unroll
        for (int t = 1; t < 16; t++) m = fmaxf(m, c[t]);
        float e[16], sum = 0.f;
#pragma unroll
        for (int t = 0; t < 16; t++) { e[t] = expf(c[t] - m); sum += e[t]; }
        const float f = sw8[q * 8 + j] / sum;
#pragma unroll
        for (int t = 0; t < 16; t++) c[t] = e[t] * f;
    }
    __syncthreads();

    {
        const int q = tid >> 4, dg = tid & 15;
        float a0 = 0.f, a1 = 0.f, b0 = 0.f, b1 = 0.f;
#pragma unroll
        for (int j = 0; j < 8; j++) {
            const int rbase = sidx[q * 8 + j] * 16;
            const float* cwr = &cw[q * 128 + j * 16];
#pragma unroll
            for (int t = 0; t < 16; t++) {
                const float w = cwr[t];
                const uint32_t* vr = (const uint32_t*)kv + (rbase + t) * 33;
                float2 va = __half22float2(*(const __half2*)&vr[dg]);
                float2 vb = __half22float2(*(const __half2*)&vr[dg + 16]);
                a0 = fmaf(w, va.x, a0);
                a1 = fmaf(w, va.y, a1);
                b0 = fmaf(w, vb.x, b0);
                b1 = fmaf(w, vb.y, b1);
            }
        }
        const size_t off = (size_t)(qbase + q) * 512 + h * 64;
        *(__half2*)&g_at_h[off + 2 * dg]      = __floats2half2_rn(a0, a1);
        *(__half2*)&g_at_h[off + 32 + 2 * dg] = __floats2half2_rn(b0, b1);
    }
}

// ---------------------------------------------------------------------------
extern "C" void kernel_launch(void* const* d_in, const int* in_sizes, int n_in,
                              void* d_out, int out_size) {
    const float* queries        = (const float*)d_in[0];
    const float* stat_keys      = (const float*)d_in[1];
    const float* token_keys     = (const float*)d_in[2];
    const float* values         = (const float*)d_in[3];
    const int*   stat_valid_len = (const int*)  d_in[4];
    WPtrs ws;
    for (int i = 0; i < 6; i++) ws.p[i] = (const float*)d_in[5 + i];
    float* out = (float*)d_out;

    __half *cq_h, *cq_l, *csk_h, *csk_l;
    __half *wh, *wl, *at_h, *ktk16, *v16h;
    float *q_stat, *q_tok, *k_stat;
    cudaGetSymbolAddress((void**)&cq_h,  g_cq_h);  cudaGetSymbolAddress((void**)&cq_l,  g_cq_l);
    cudaGetSymbolAddress((void**)&csk_h, g_csk_h); cudaGetSymbolAddress((void**)&csk_l, g_csk_l);
    cudaGetSymbolAddress((void**)&wh,    g_wh);    cudaGetSymbolAddress((void**)&wl,    g_wl);
    cudaGetSymbolAddress((void**)&at_h,  g_at_h);
    cudaGetSymbolAddress((void**)&ktk16, g_ktk16); cudaGetSymbolAddress((void**)&v16h,  g_v16h);
    cudaGetSymbolAddress((void**)&q_stat, g_q_stat);
    cudaGetSymbolAddress((void**)&q_tok,  g_q_tok);
    cudaGetSymbolAddress((void**)&k_stat, g_k_stat);

    const size_t WSZ = (size_t)512 * 512;
    constexpr int SMEM = 2 * (2 * 128 * 80 + 2 * 128 * 80);  // 81920
    cudaFuncSetAttribute(gemm_batched, cudaFuncAttributeMaxDynamicSharedMemorySize, SMEM);
    cudaFuncSetAttribute(attn2, cudaFuncAttributeMaxDynamicSharedMemorySize, ATTN_SMEM);

    // 1) prep: weights + small input conversion (q, sk only)
    prep_w<<<dim3(16, 16, 6), dim3(32, 8)>>>(ws);
    conv_act<<<dim3(256, 2), 256>>>(queries, stat_keys);

    // 2) all five projections in one launch (560 CTAs)
    GemmBatch gb;
    // seg 0: queries @ [Wq_stat|Wq_token] (3-term, fp32 split out)
    gb.Ah[0] = cq_h;  gb.Al[0] = cq_l;  gb.Bh[0] = wh;           gb.Bl[0] = wl;
    gb.F[0] = nullptr;
    gb.C0[0] = q_stat; gb.C1[0] = q_tok; gb.Ho[0] = nullptr; gb.nbx[0] = 8; gb.cnt[0] = 32;
    // seg 1: stat_keys @ Wk_stat (3-term, fp32 out)
    gb.Ah[1] = csk_h; gb.Al[1] = csk_l; gb.Bh[1] = wh + 2 * WSZ; gb.Bl[1] = wl + 2 * WSZ;
    gb.F[1] = nullptr;
    gb.C0[1] = k_stat; gb.C1[1] = nullptr; gb.Ho[1] = nullptr; gb.nbx[1] = 4; gb.cnt[1] = 16;
    // seg 2: gathered token_keys (fp32 in-kernel convert) @ Wk_token (2-term, fp16 out)
    gb.Ah[2] = nullptr; gb.Al[2] = nullptr; gb.Bh[2] = wh + 3 * WSZ; gb.Bl[2] = wl + 3 * WSZ;
    gb.F[2] = token_keys;
    gb.C0[2] = nullptr; gb.C1[2] = nullptr; gb.Ho[2] = ktk16; gb.nbx[2] = 4; gb.cnt[2] = 256;
    // seg 3: gathered values @ Wv (2-term, fp16 out)
    gb.Ah[3] = nullptr; gb.Al[3] = nullptr; gb.Bh[3] = wh + 4 * WSZ; gb.Bl[3] = wl + 4 * WSZ;
    gb.F[3] = values;
    gb.C0[3] = nullptr; gb.C1[3] = nullptr; gb.Ho[3] = v16h; gb.nbx[3] = 4; gb.cnt[3] = 256;
    gemm_batched<<<560, 256, SMEM>>>(gb);

    // 3) attention v2
    attn2<<<dim3(64, 2), 512, ATTN_SMEM>>>(stat_valid_len);

    // 4) output projection (2-term, fp32 out)
    GemmBatch go;
    go.Ah[0] = at_h; go.Al[0] = nullptr; go.Bh[0] = wh + 5 * WSZ; go.Bl[0] = wl + 5 * WSZ;
    go.F[0] = nullptr;
    go.C0[0] = out;  go.C1[0] = nullptr; go.Ho[0] = nullptr; go.nbx[0] = 4; go.cnt[0] = 16;
    go.cnt[1] = go.cnt[2] = go.cnt[3] = 0x7fffffff;
    go.Ah[1] = go.Ah[2] = go.Ah[3] = at_h; go.Al[1] = go.Al[2] = go.Al[3] = nullptr;
    go.Bh[1] = go.Bh[2] = go.Bh[3] = wh;   go.Bl[1] = go.Bl[2] = go.Bl[3] = wl;
    go.F[1] = go.F[2] = go.F[3] = nullptr;
    go.C0[1] = go.C0[2] = go.C0[3] = out;  go.C1[1] = go.C1[2] = go.C1[3] = nullptr;
    go.Ho[1] = go.Ho[2] = go.Ho[3] = nullptr;
    go.nbx[1] = go.nbx[2] = go.nbx[3] = 4;
    gemm_batched<<<16, 256, SMEM>>>(go);
}

// round 12
// speedup vs baseline: 1.1730x; 1.1730x over previous
#include <cuda_runtime.h>
#include <cuda_fp16.h>
#include <cstdint>
#include <math.h>

#define B_   8
#define Q_   64
#define S_   64
#define T_   64
#define H_   8
#define DH_  64
#define NH_  512
#define NEGV (-1e6f)

// ---------------------------------------------------------------------------
// Scratch (device globals)
// ---------------------------------------------------------------------------
__device__ __half g_cq_h [512 * 512],  g_cq_l [512 * 512];    // queries hi/lo
__device__ __half g_csk_h[512 * 512],  g_csk_l[512 * 512];    // stat_keys hi/lo
__device__ __half g_ctk_h[8192 * 512];                        // gathered token_keys fp16
__device__ __half g_cv_h [8192 * 512];                        // gathered values fp16
__device__ __half g_wh[6 * 512 * 512], g_wl[6 * 512 * 512];   // W^T [N,K] fp16 hi/lo
__device__ float g_q_stat[512 * 512];
__device__ float g_q_tok [512 * 512];
__device__ float g_k_stat[512 * 512];
__device__ __half g_ktk16[8192 * 512];                        // projected token keys (fp16)
__device__ __half g_v16h [8192 * 512];                        // projected values (fp16)
__device__ __half g_at_h[512 * 512];                          // attn out fp16

// ---------------------------------------------------------------------------
// helpers
// ---------------------------------------------------------------------------
__device__ __forceinline__ uint32_t smem_u32(const void* p) {
    uint32_t a;
    asm("{ .reg .u64 t; cvta.to.shared.u64 t, %1; cvt.u32.u64 %0, t; }" : "=r"(a) : "l"(p));
    return a;
}
__device__ __forceinline__ void ldsm_x4(uint32_t* r, uint32_t addr) {
    asm volatile("ldmatrix.sync.aligned.m8n8.x4.shared.b16 {%0,%1,%2,%3}, [%4];"
        : "=r"(r[0]), "=r"(r[1]), "=r"(r[2]), "=r"(r[3]) : "r"(addr));
}
__device__ __forceinline__ void ldsm_x2(uint32_t* r, uint32_t addr) {
    asm volatile("ldmatrix.sync.aligned.m8n8.x2.shared.b16 {%0,%1}, [%2];"
        : "=r"(r[0]), "=r"(r[1]) : "r"(addr));
}
__device__ __forceinline__ void mma16816(float* d, const uint32_t* a, const uint32_t* b) {
    asm volatile("mma.sync.aligned.m16n8k16.row.col.f32.f16.f16.f32 "
        "{%0,%1,%2,%3}, {%4,%5,%6,%7}, {%8,%9}, {%0,%1,%2,%3};"
        : "+f"(d[0]), "+f"(d[1]), "+f"(d[2]), "+f"(d[3])
        : "r"(a[0]), "r"(a[1]), "r"(a[2]), "r"(a[3]), "r"(b[0]), "r"(b[1]));
}
__device__ __forceinline__ void cp16(uint32_t dst, const void* src) {
    asm volatile("cp.async.cg.shared.global [%0], [%1], 16;" :: "r"(dst), "l"(src));
}
#define CP_COMMIT() asm volatile("cp.async.commit_group;" ::: "memory")
#define CP_WAIT1()  asm volatile("cp.async.wait_group 1;" ::: "memory")
#define CP_WAIT0()  asm volatile("cp.async.wait_group 0;" ::: "memory")

__device__ __forceinline__ uint32_t pack2h(float a, float b) {
    return (uint32_t)__half_as_ushort(__float2half(a)) |
           ((uint32_t)__half_as_ushort(__float2half(b)) << 16);
}

// ---------------------------------------------------------------------------
// Convert inputs: q/sk -> fp16 hi/lo; gathered tk/v -> fp16 hi only
// ---------------------------------------------------------------------------
__global__ __launch_bounds__(256)
void conv_act(const float* __restrict__ q, const float* __restrict__ sk,
              const float* __restrict__ tk, const float* __restrict__ v) {
    const int z = blockIdx.y;
    const int rows = (z < 2) ? 512 : 8192;
    const int idx = blockIdx.x * 256 + threadIdx.x;
    if (idx >= rows * 128) return;
    const int r = idx >> 7, c4 = idx & 127;

    if (z < 2) {
        const float* src = z ? sk : q;
        __half* dh = z ? g_csk_h : g_cq_h;
        __half* dl = z ? g_csk_l : g_cq_l;
        float4 x = *(const float4*)&src[(size_t)r * 512 + c4 * 4];
        __half h0 = __float2half(x.x), h1 = __float2half(x.y),
               h2 = __float2half(x.z), h3 = __float2half(x.w);
        uint2 hh, ll;
        hh.x = (uint32_t)__half_as_ushort(h0) | ((uint32_t)__half_as_ushort(h1) << 16);
        hh.y = (uint32_t)__half_as_ushort(h2) | ((uint32_t)__half_as_ushort(h3) << 16);
        ll.x = pack2h(x.x - __half2float(h0), x.y - __half2float(h1));
        ll.y = pack2h(x.z - __half2float(h2), x.w - __half2float(h3));
        *(uint2*)&dh[(size_t)r * 512 + c4 * 4] = hh;
        *(uint2*)&dl[(size_t)r * 512 + c4 * 4] = ll;
    } else {
        const int sr = (r >> 4) * 64 + 48 + (r & 15);
        const float* src = (z == 2) ? tk : v;
        __half* dh = (z == 2) ? g_ctk_h : g_cv_h;
        float4 x = *(const float4*)&src[(size_t)sr * 512 + c4 * 4];
        uint2 hh;
        hh.x = pack2h(x.x, x.y);
        hh.y = pack2h(x.z, x.w);
        *(uint2*)&dh[(size_t)r * 512 + c4 * 4] = hh;
    }
}

// ---------------------------------------------------------------------------
// Weight prep: transpose W[K,N] fp32 -> Wt[N,K] fp16 hi/lo (6 weights)
// ---------------------------------------------------------------------------
struct WPtrs { const float* p[6]; };

__global__ __launch_bounds__(256)
void prep_w(WPtrs ws) {
    __shared__ float t[32][33];
    const int widx = blockIdx.z;
    const float* W = ws.p[widx];
    __half* hiw = g_wh + (size_t)widx * 512 * 512;
    __half* low = g_wl + (size_t)widx * 512 * 512;
    const int n0 = blockIdx.x * 32, k0 = blockIdx.y * 32;
    const int tx = threadIdx.x, ty = threadIdx.y;
#pragma unroll
    for (int i = ty; i < 32; i += 8)
        t[i][tx] = W[(size_t)(k0 + i) * 512 + n0 + tx];
    __syncthreads();
#pragma unroll
    for (int i = ty; i < 32; i += 8) {
        float v = t[tx][i];
        __half h = __float2half(v);
        hiw[(size_t)(n0 + i) * 512 + k0 + tx] = h;
        low[(size_t)(n0 + i) * 512 + k0 + tx] = __float2half(v - __half2float(h));
    }
}

// ---------------------------------------------------------------------------
// Batched fp16 hi/lo GEMM, cp.async 2-stage pipeline.
//   Al != nullptr -> 3-term (AhBh + AhBl + AlBh); else 2-term.
//   Ho != nullptr -> fp16 output; else fp32 (C0/C1 split).
// ---------------------------------------------------------------------------
struct GemmBatch {
    const __half *Ah[4], *Al[4], *Bh[4], *Bl[4];
    float *C0[4], *C1[4];
    __half *Ho[4];
    int nbx[4];
    int cnt[4];
};

__global__ __launch_bounds__(256)
void gemm_batched(GemmBatch args) {
    constexpr int MT = 4;
    constexpr uint32_t ABYTES = 128 * 80;
    constexpr uint32_t BBYTES = 128 * 80;
    constexpr uint32_t STG    = 2 * ABYTES + 2 * BBYTES;
    extern __shared__ char smem[];
    const uint32_t sb = smem_u32(smem);

    int id = blockIdx.x, s = 0;
#pragma unroll
    for (int i = 0; i < 3; i++) {
        bool adv = (id >= args.cnt[s]);
        if (adv) { id -= args.cnt[s]; s++; }
    }
    const __half* Ah = args.Ah[s];
    const __half* Al = args.Al[s];
    const __half* Bh = args.Bh[s];
    const __half* Bl = args.Bl[s];
    float* C0 = args.C0[s];
    float* C1 = args.C1[s];
    __half* Ho = args.Ho[s];
    const int nbx = args.nbx[s];
    const int bx = id % nbx, by = id / nbx;
    const int m0 = by * 128, n0 = bx * 128;

    const int tid = threadIdx.x;
    const int wid = tid >> 5, lane = tid & 31;
    const int wm = wid >> 2, wn = wid & 3;

    const uint32_t rowA = (uint32_t)(wm * 64 + (lane & 7) + ((lane >> 3) & 1) * 8);
    const uint32_t colA = (uint32_t)(((lane >> 4) & 1) * 16);
    const uint32_t oAh = rowA * 80 + colA;
    const uint32_t oAl = oAh + ABYTES;
    const uint32_t rowB = (uint32_t)(wn * 32 + (lane & 7));
    const uint32_t colB = (uint32_t)(((lane >> 3) & 1) * 16);
    const uint32_t oBh = 2 * ABYTES + rowB * 80 + colB;
    const uint32_t oBl = oBh + BBYTES;

    float acc[MT][4][4];
#pragma unroll
    for (int i = 0; i < MT; i++)
#pragma unroll
        for (int j = 0; j < 4; j++)
#pragma unroll
            for (int e = 0; e < 4; e++) acc[i][j][e] = 0.f;

    auto load_stage = [&](int st, int kc) {
        const int k0 = kc * 32;
        const uint32_t base = sb + st * STG;
#pragma unroll
        for (int i = 0; i < 2; i++) {
            int c = tid + i * 256;
            int r = c >> 2, qq = c & 3;
            uint32_t dst = base + r * 80 + qq * 16;
            const size_t ga = (size_t)(m0 + r) * 512 + k0 + qq * 8;
            cp16(dst, Ah + ga);
            if (Al) cp16(dst + ABYTES, Al + ga);
            uint32_t dstB = base + 2 * ABYTES + r * 80 + qq * 16;
            const size_t gb = (size_t)(n0 + r) * 512 + k0 + qq * 8;
            cp16(dstB, Bh + gb);
            cp16(dstB + BBYTES, Bl + gb);
        }
    };

    load_stage(0, 0); CP_COMMIT();
    load_stage(1, 1); CP_COMMIT();

    for (int kc = 0; kc < 16; kc++) {
        if (kc < 15) { CP_WAIT1(); } else { CP_WAIT0(); }
        __syncthreads();
        const uint32_t so = sb + (kc & 1) * STG;
#pragma unroll
        for (int ks = 0; ks < 2; ks++) {
            uint32_t bh[4][2], bl[4][2];
#pragma unroll
            for (int ni = 0; ni < 4; ni++) ldsm_x2(bh[ni], so + oBh + ni * 640 + ks * 32);
#pragma unroll
            for (int ni = 0; ni < 4; ni++) ldsm_x2(bl[ni], so + oBl + ni * 640 + ks * 32);
#pragma unroll
            for (int mi = 0; mi < MT; mi++) {
                uint32_t ah[4];
                ldsm_x4(ah, so + oAh + mi * 1280 + ks * 32);
#pragma unroll
                for (int ni = 0; ni < 4; ni++) mma16816(acc[mi][ni], ah, bh[ni]);
#pragma unroll
                for (int ni = 0; ni < 4; ni++) mma16816(acc[mi][ni], ah, bl[ni]);
                if (Al) {
                    uint32_t al[4];
                    ldsm_x4(al, so + oAl + mi * 1280 + ks * 32);
#pragma unroll
                    for (int ni = 0; ni < 4; ni++) mma16816(acc[mi][ni], al, bh[ni]);
                }
            }
        }
        __syncthreads();
        if (kc + 2 < 16) { load_stage(kc & 1, kc + 2); }
        CP_COMMIT();
    }

    const int mrow = m0 + wm * 64 + (lane >> 2);
    const int ncol = n0 + wn * 32 + (lane & 3) * 2;
#pragma unroll
    for (int mi = 0; mi < MT; mi++) {
#pragma unroll
        for (int ni = 0; ni < 4; ni++) {
            int col = ncol + ni * 8;
            int r0 = mrow + mi * 16;
            if (Ho) {
                *(__half2*)&Ho[(size_t)r0 * 512 + col] =
                    __floats2half2_rn(acc[mi][ni][0], acc[mi][ni][1]);
                *(__half2*)&Ho[(size_t)(r0 + 8) * 512 + col] =
                    __floats2half2_rn(acc[mi][ni][2], acc[mi][ni][3]);
            } else {
                float* dst = (C1 && col >= 512) ? (C1 + col - 512) : (C0 + col);
                *(float2*)&dst[(size_t)r0 * 512]       = make_float2(acc[mi][ni][0], acc[mi][ni][1]);
                *(float2*)&dst[(size_t)(r0 + 8) * 512] = make_float2(acc[mi][ni][2], acc[mi][ni][3]);
            }
        }
    }
}

// ---------------------------------------------------------------------------
// Hierarchical attention v2 (round 9, passing): block per (b,h,q-half).
// Emits fp16 attn output (hi only).
// ---------------------------------------------------------------------------
#define ATTN_SMEM 195584

__global__ __launch_bounds__(512)
void attn2(const int* __restrict__ valid_lens) {
    extern __shared__ char sm[];
    __half* kv   = (__half*)sm;                                 // [1024][66]
    float*  ks_t = (float*)(sm + 135168);                       // [64][68]
    float*  qs   = (float*)(sm + 135168 + 17408);               // [32][64]
    float*  qt   = qs + 2048;
    float*  sc   = qt + 2048;
    float*  cw   = sc + 2048;                                   // [32][128]
    int*    sidx = (int*)(cw + 4096);                           // [32][8]
    float*  sw8  = (float*)(sidx + 256);                        // [32][8]

    const int bh = blockIdx.x;
    const int b = bh >> 3, h = bh & 7;
    const int qh = blockIdx.y;
    const int qbase = b * 64 + qh * 32;
    const int tid = threadIdx.x, wid = tid >> 5, lane = tid & 31;
    const float scale = 0.125f;

#pragma unroll
    for (int k = 0; k < 2; k++) {
        int i4 = tid + k * 512;
        int s = i4 >> 4, dq = i4 & 15;
        float4 v = *(const float4*)&g_k_stat[(size_t)(b * 64 + s) * 512 + h * 64 + dq * 4];
        ks_t[(dq * 4 + 0) * 68 + s] = v.x;
        ks_t[(dq * 4 + 1) * 68 + s] = v.y;
        ks_t[(dq * 4 + 2) * 68 + s] = v.z;
        ks_t[(dq * 4 + 3) * 68 + s] = v.w;
    }
    {
        int q = tid >> 4, dq = tid & 15;
        *(float4*)&qs[q * 64 + dq * 4] =
            *(const float4*)&g_q_stat[(size_t)(qbase + q) * 512 + h * 64 + dq * 4];
        *(float4*)&qt[q * 64 + dq * 4] =
            *(const float4*)&g_q_tok[(size_t)(qbase + q) * 512 + h * 64 + dq * 4];
    }
#pragma unroll
    for (int k = 0; k < 16; k++) {
        int idx = tid + k * 512;
        int r = idx >> 3, c = idx & 7;
        uint4 v = *(const uint4*)&g_ktk16[((size_t)(b * 1024) + r) * 512 + h * 64 + c * 8];
        uint32_t* dst = (uint32_t*)kv + r * 33 + c * 4;
        dst[0] = v.x; dst[1] = v.y; dst[2] = v.z; dst[3] = v.w;
    }
    __syncthreads();

    const int vlen = valid_lens[b];

    {
        const int q = tid >> 4, sg = tid & 15;
        float a0 = 0.f, a1 = 0.f, a2 = 0.f, a3 = 0.f;
        const float* qrow = &qs[q * 64];
#pragma unroll
        for (int d = 0; d < 64; d++) {
            float qv = qrow[d];
            float4 kf = *(const float4*)&ks_t[d * 68 + sg * 4];
            a0 = fmaf(qv, kf.x, a0);
            a1 = fmaf(qv, kf.y, a1);
            a2 = fmaf(qv, kf.z, a2);
            a3 = fmaf(qv, kf.w, a3);
        }
        const int s0 = sg * 4;
        sc[q * 64 + s0 + 0] = (s0 + 0 < vlen) ? a0 * scale : NEGV;
        sc[q * 64 + s0 + 1] = (s0 + 1 < vlen) ? a1 * scale : NEGV;
        sc[q * 64 + s0 + 2] = (s0 + 2 < vlen) ? a2 * scale : NEGV;
        sc[q * 64 + s0 + 3] = (s0 + 3 < vlen) ? a3 * scale : NEGV;
    }
    __syncthreads();

    for (int rep = 0; rep < 2; rep++) {
        const int q = wid * 2 + rep;
        float v0 = sc[q * 64 + lane], v1 = sc[q * 64 + lane + 32];
        int i0 = lane, i1 = lane + 32;
        float vals[8];
#pragma unroll
        for (int j = 0; j < 8; j++) {
            float m; int mi;
            if (v0 >= v1) { m = v0; mi = i0; } else { m = v1; mi = i1; }
#pragma unroll
            for (int o = 16; o; o >>= 1) {
                float om = __shfl_xor_sync(~0u, m, o);
                int   oi = __shfl_xor_sync(~0u, mi, o);
                if (om > m || (om == m && oi < mi)) { m = om; mi = oi; }
            }
            if (lane == 0) { sidx[q * 8 + j] = mi; vals[j] = m; }
            if (i0 == mi) v0 = -3.0e38f;
            if (i1 == mi) v1 = -3.0e38f;
        }
        if (lane == 0) {
            const float m = vals[0];
            float e[8], sum = 0.f;
#pragma unroll
            for (int j = 0; j < 8; j++) { e[j] = expf(vals[j] - m); sum += e[j]; }
            const float inv = 1.f / sum;
#pragma unroll
            for (int j = 0; j < 8; j++) sw8[q * 8 + j] = e[j] * inv;
        }
    }
    __syncthreads();

    {
        const int t = lane >> 1, hf = lane & 1;
        for (int kk = 0; kk < 16; kk++) {
            const int q = wid * 2 + (kk >> 3);
            const int j = kk & 7;
            const int row = sidx[q * 8 + j] * 16 + t;
            const uint32_t* kr = (const uint32_t*)kv + row * 33 + hf * 16;
            const float* qr = &qt[q * 64 + hf * 32];
            float acc = 0.f;
#pragma unroll
            for (int it = 0; it < 16; it++) {
                float2 kf = __half22float2(*(const __half2*)&kr[it]);
                float2 q2 = *(const float2*)&qr[it * 2];
                acc = fmaf(q2.x, kf.x, acc);
                acc = fmaf(q2.y, kf.y, acc);
            }
            acc += __shfl_xor_sync(~0u, acc, 1);
            if (hf == 0) cw[q * 128 + j * 16 + t] = acc * scale;
        }
    }
    __syncthreads();

#pragma unroll
    for (int k = 0; k < 16; k++) {
        int idx = tid + k * 512;
        int r = idx >> 3, c = idx & 7;
        uint4 v = *(const uint4*)&g_v16h[((size_t)(b * 1024) + r) * 512 + h * 64 + c * 8];
        uint32_t* dst = (uint32_t*)kv + r * 33 + c * 4;
        dst[0] = v.x; dst[1] = v.y; dst[2] = v.z; dst[3] = v.w;
    }
    if (tid < 256) {
        const int q = tid >> 3, j = tid & 7;
        float* c = &cw[q * 128 + j * 16];
        float m = c[0];
#pragma unroll
        for (int t = 1; t < 16; t++) m = fmaxf(m, c[t]);
        float e[16], sum = 0.f;
#pragma unroll
        for (int t = 0; t < 16; t++) { e[t] = expf(c[t] - m); sum += e[t]; }
        const float f = sw8[q * 8 + j] / sum;
#pragma unroll
        for (int t = 0; t < 16; t++) c[t] = e[t] * f;
    }
    __syncthreads();

    {
        const int q = tid >> 4, dg = tid & 15;
        float a0 = 0.f, a1 = 0.f, b0 = 0.f, b1 = 0.f;
#pragma unroll
        for (int j = 0; j < 8; j++) {
            const int rbase = sidx[q * 8 + j] * 16;
            const float* cwr = &cw[q * 128 + j * 16];
#pragma unroll
            for (int t = 0; t < 16; t++) {
                const float w = cwr[t];
                const uint32_t* vr = (const uint32_t*)kv + (rbase + t) * 33;
                float2 va = __half22float2(*(const __half2*)&vr[dg]);
                float2 vb = __half22float2(*(const __half2*)&vr[dg + 16]);
                a0 = fmaf(w, va.x, a0);
                a1 = fmaf(w, va.y, a1);
                b0 = fmaf(w, vb.x, b0);
                b1 = fmaf(w, vb.y, b1);
            }
        }
        const size_t off = (size_t)(qbase + q) * 512 + h * 64;
        *(__half2*)&g_at_h[off + 2 * dg]      = __floats2half2_rn(a0, a1);
        *(__half2*)&g_at_h[off + 32 + 2 * dg] = __floats2half2_rn(b0, b1);
    }
}

// ---------------------------------------------------------------------------
extern "C" void kernel_launch(void* const* d_in, const int* in_sizes, int n_in,
                              void* d_out, int out_size) {
    const float* queries        = (const float*)d_in[0];
    const float* stat_keys      = (const float*)d_in[1];
    const float* token_keys     = (const float*)d_in[2];
    const float* values         = (const float*)d_in[3];
    const int*   stat_valid_len = (const int*)  d_in[4];
    WPtrs ws;
    for (int i = 0; i < 6; i++) ws.p[i] = (const float*)d_in[5 + i];
    float* out = (float*)d_out;

    __half *cq_h, *cq_l, *csk_h, *csk_l, *ctk_h, *cv_h;
    __half *wh, *wl, *at_h, *ktk16, *v16h;
    float *q_stat, *q_tok, *k_stat;
    cudaGetSymbolAddress((void**)&cq_h,  g_cq_h);  cudaGetSymbolAddress((void**)&cq_l,  g_cq_l);
    cudaGetSymbolAddress((void**)&csk_h, g_csk_h); cudaGetSymbolAddress((void**)&csk_l, g_csk_l);
    cudaGetSymbolAddress((void**)&ctk_h, g_ctk_h); cudaGetSymbolAddress((void**)&cv_h,  g_cv_h);
    cudaGetSymbolAddress((void**)&wh,    g_wh);    cudaGetSymbolAddress((void**)&wl,    g_wl);
    cudaGetSymbolAddress((void**)&at_h,  g_at_h);
    cudaGetSymbolAddress((void**)&ktk16, g_ktk16); cudaGetSymbolAddress((void**)&v16h,  g_v16h);
    cudaGetSymbolAddress((void**)&q_stat, g_q_stat);
    cudaGetSymbolAddress((void**)&q_tok,  g_q_tok);
    cudaGetSymbolAddress((void**)&k_stat, g_k_stat);

    const size_t WSZ = (size_t)512 * 512;
    constexpr int SMEM = 2 * (2 * 128 * 80 + 2 * 128 * 80);  // 81920
    cudaFuncSetAttribute(gemm_batched, cudaFuncAttributeMaxDynamicSharedMemorySize, SMEM);
    cudaFuncSetAttribute(attn2, cudaFuncAttributeMaxDynamicSharedMemorySize, ATTN_SMEM);

    // 1) prep: weights + input conversion (q/sk hi-lo; gathered tk/v fp16)
    prep_w<<<dim3(16, 16, 6), dim3(32, 8)>>>(ws);
    conv_act<<<dim3(4096, 4), 256>>>(queries, stat_keys, token_keys, values);

    // 2) all five projections in one launch (560 CTAs)
    GemmBatch gb;
    // seg 0: queries @ [Wq_stat|Wq_token] (3-term, fp32 split out)
    gb.Ah[0] = cq_h;  gb.Al[0] = cq_l;  gb.Bh[0] = wh;           gb.Bl[0] = wl;
    gb.C0[0] = q_stat; gb.C1[0] = q_tok; gb.Ho[0] = nullptr; gb.nbx[0] = 8; gb.cnt[0] = 32;
    // seg 1: stat_keys @ Wk_stat (3-term, fp32 out)
    gb.Ah[1] = csk_h; gb.Al[1] = csk_l; gb.Bh[1] = wh + 2 * WSZ; gb.Bl[1] = wl + 2 * WSZ;
    gb.C0[1] = k_stat; gb.C1[1] = nullptr; gb.Ho[1] = nullptr; gb.nbx[1] = 4; gb.cnt[1] = 16;
    // seg 2: token_keys16 @ Wk_token (2-term, fp16 out)
    gb.Ah[2] = ctk_h; gb.Al[2] = nullptr; gb.Bh[2] = wh + 3 * WSZ; gb.Bl[2] = wl + 3 * WSZ;
    gb.C0[2] = nullptr; gb.C1[2] = nullptr; gb.Ho[2] = ktk16; gb.nbx[2] = 4; gb.cnt[2] = 256;
    // seg 3: values16 @ Wv (2-term, fp16 out)
    gb.Ah[3] = cv_h;  gb.Al[3] = nullptr; gb.Bh[3] = wh + 4 * WSZ; gb.Bl[3] = wl + 4 * WSZ;
    gb.C0[3] = nullptr; gb.C1[3] = nullptr; gb.Ho[3] = v16h; gb.nbx[3] = 4; gb.cnt[3] = 256;
    gemm_batched<<<560, 256, SMEM>>>(gb);

    // 3) attention v2
    attn2<<<dim3(64, 2), 512, ATTN_SMEM>>>(stat_valid_len);

    // 4) output projection (2-term, fp32 out)
    GemmBatch go;
    go.Ah[0] = at_h; go.Al[0] = nullptr; go.Bh[0] = wh + 5 * WSZ; go.Bl[0] = wl + 5 * WSZ;
    go.C0[0] = out;  go.C1[0] = nullptr; go.Ho[0] = nullptr; go.nbx[0] = 4; go.cnt[0] = 16;
    go.cnt[1] = go.cnt[2] = go.cnt[3] = 0x7fffffff;
    go.Ah[1] = go.Ah[2] = go.Ah[3] = at_h; go.Al[1] = go.Al[2] = go.Al[3] = nullptr;
    go.Bh[1] = go.Bh[2] = go.Bh[3] = wh;   go.Bl[1] = go.Bl[2] = go.Bl[3] = wl;
    go.C0[1] = go.C0[2] = go.C0[3] = out;  go.C1[1] = go.C1[2] = go.C1[3] = nullptr;
    go.Ho[1] = go.Ho[2] = go.Ho[3] = nullptr;
    go.nbx[1] = go.nbx[2] = go.nbx[3] = 4;
    gemm_batched<<<16, 256, SMEM>>>(go);
}

// round 13
// speedup vs baseline: 1.2474x; 1.0634x over previous
#include <cuda_runtime.h>
#include <cuda_fp16.h>
#include <cstdint>
#include <math.h>

#define B_   8
#define Q_   64
#define S_   64
#define T_   64
#define H_   8
#define DH_  64
#define NH_  512
#define NEGV (-1e6f)

// ---------------------------------------------------------------------------
// Scratch (device globals)
// ---------------------------------------------------------------------------
__device__ __half g_cq_h [512 * 512],  g_cq_l [512 * 512];    // queries hi/lo
__device__ __half g_csk_h[512 * 512],  g_csk_l[512 * 512];    // stat_keys hi/lo
__device__ __half g_ctk_h[8192 * 512];                        // gathered token_keys fp16
__device__ __half g_cv_h [8192 * 512];                        // gathered values fp16
__device__ __half g_wh[6 * 512 * 512], g_wl[6 * 512 * 512];   // W^T [N,K] fp16 hi/lo
__device__ float g_q_stat[512 * 512];
__device__ float g_q_tok [512 * 512];
__device__ float g_k_stat[512 * 512];
__device__ __half g_ktk16[8192 * 512];                        // projected token keys (fp16)
__device__ __half g_v16h [8192 * 512];                        // projected values (fp16)
__device__ __half g_at_h[512 * 512];                          // attn out fp16

// ---------------------------------------------------------------------------
// helpers
// ---------------------------------------------------------------------------
__device__ __forceinline__ uint32_t smem_u32(const void* p) {
    uint32_t a;
    asm("{ .reg .u64 t; cvta.to.shared.u64 t, %1; cvt.u32.u64 %0, t; }" : "=r"(a) : "l"(p));
    return a;
}
__device__ __forceinline__ void ldsm_x4(uint32_t* r, uint32_t addr) {
    asm volatile("ldmatrix.sync.aligned.m8n8.x4.shared.b16 {%0,%1,%2,%3}, [%4];"
        : "=r"(r[0]), "=r"(r[1]), "=r"(r[2]), "=r"(r[3]) : "r"(addr));
}
__device__ __forceinline__ void ldsm_x2(uint32_t* r, uint32_t addr) {
    asm volatile("ldmatrix.sync.aligned.m8n8.x2.shared.b16 {%0,%1}, [%2];"
        : "=r"(r[0]), "=r"(r[1]) : "r"(addr));
}
__device__ __forceinline__ void mma16816(float* d, const uint32_t* a, const uint32_t* b) {
    asm volatile("mma.sync.aligned.m16n8k16.row.col.f32.f16.f16.f32 "
        "{%0,%1,%2,%3}, {%4,%5,%6,%7}, {%8,%9}, {%0,%1,%2,%3};"
        : "+f"(d[0]), "+f"(d[1]), "+f"(d[2]), "+f"(d[3])
        : "r"(a[0]), "r"(a[1]), "r"(a[2]), "r"(a[3]), "r"(b[0]), "r"(b[1]));
}
__device__ __forceinline__ void cp16(uint32_t dst, const void* src) {
    asm volatile("cp.async.cg.shared.global [%0], [%1], 16;" :: "r"(dst), "l"(src));
}
#define CP_COMMIT() asm volatile("cp.async.commit_group;" ::: "memory")
#define CP_WAIT1()  asm volatile("cp.async.wait_group 1;" ::: "memory")
#define CP_WAIT0()  asm volatile("cp.async.wait_group 0;" ::: "memory")

__device__ __forceinline__ uint32_t pack2h(float a, float b) {
    return (uint32_t)__half_as_ushort(__float2half(a)) |
           ((uint32_t)__half_as_ushort(__float2half(b)) << 16);
}

// ---------------------------------------------------------------------------
// Fused prep: weight transpose+split (blocks [0,1536)) and input conversion
// (blocks [1536,10240)) in ONE launch.
// ---------------------------------------------------------------------------
struct WPtrs { const float* p[6]; };

__global__ __launch_bounds__(256)
void prep_all(WPtrs ws, const float* __restrict__ q, const float* __restrict__ sk,
              const float* __restrict__ tk, const float* __restrict__ v) {
    __shared__ float t[32][33];
    const int bid = blockIdx.x;
    const int tid = threadIdx.x;

    if (bid < 1536) {
        // ---- weight transpose: W[K,N] fp32 -> Wt[N,K] fp16 hi/lo ----
        const int widx = bid / 256;
        const int rem = bid % 256;
        const int n0 = (rem & 15) * 32, k0 = (rem >> 4) * 32;
        const float* W = ws.p[widx];
        __half* hiw = g_wh + (size_t)widx * 512 * 512;
        __half* low = g_wl + (size_t)widx * 512 * 512;
        const int tx = tid & 31, ty = tid >> 5;
#pragma unroll
        for (int i = ty; i < 32; i += 8)
            t[i][tx] = W[(size_t)(k0 + i) * 512 + n0 + tx];
        __syncthreads();
#pragma unroll
        for (int i = ty; i < 32; i += 8) {
            float val = t[tx][i];
            __half h = __float2half(val);
            hiw[(size_t)(n0 + i) * 512 + k0 + tx] = h;
            low[(size_t)(n0 + i) * 512 + k0 + tx] = __float2half(val - __half2float(h));
        }
        return;
    }

    // ---- input conversion ----
    const int cid = bid - 1536;
    int z, base;
    if (cid < 256)       { z = 0; base = cid; }
    else if (cid < 512)  { z = 1; base = cid - 256; }
    else if (cid < 4608) { z = 2; base = cid - 512; }
    else                 { z = 3; base = cid - 4608; }
    const int idx = base * 256 + tid;
    const int r = idx >> 7, c4 = idx & 127;

    if (z < 2) {
        const float* src = z ? sk : q;
        __half* dh = z ? g_csk_h : g_cq_h;
        __half* dl = z ? g_csk_l : g_cq_l;
        float4 x = *(const float4*)&src[(size_t)r * 512 + c4 * 4];
        __half h0 = __float2half(x.x), h1 = __float2half(x.y),
               h2 = __float2half(x.z), h3 = __float2half(x.w);
        uint2 hh, ll;
        hh.x = (uint32_t)__half_as_ushort(h0) | ((uint32_t)__half_as_ushort(h1) << 16);
        hh.y = (uint32_t)__half_as_ushort(h2) | ((uint32_t)__half_as_ushort(h3) << 16);
        ll.x = pack2h(x.x - __half2float(h0), x.y - __half2float(h1));
        ll.y = pack2h(x.z - __half2float(h2), x.w - __half2float(h3));
        *(uint2*)&dh[(size_t)r * 512 + c4 * 4] = hh;
        *(uint2*)&dl[(size_t)r * 512 + c4 * 4] = ll;
    } else {
        const int sr = (r >> 4) * 64 + 48 + (r & 15);
        const float* src = (z == 2) ? tk : v;
        __half* dh = (z == 2) ? g_ctk_h : g_cv_h;
        float4 x = *(const float4*)&src[(size_t)sr * 512 + c4 * 4];
        uint2 hh;
        hh.x = pack2h(x.x, x.y);
        hh.y = pack2h(x.z, x.w);
        *(uint2*)&dh[(size_t)r * 512 + c4 * 4] = hh;
    }
}

// ---------------------------------------------------------------------------
// Batched fp16 hi/lo GEMM, cp.async 2-stage pipeline.
//   Al != nullptr -> + Al*Bh term.
//   Bl != nullptr -> + Ah*Bl term.
//   Ho != nullptr -> fp16 output; else fp32 (C0/C1 split).
// ---------------------------------------------------------------------------
struct GemmBatch {
    const __half *Ah[4], *Al[4], *Bh[4], *Bl[4];
    float *C0[4], *C1[4];
    __half *Ho[4];
    int nbx[4];
    int cnt[4];
};

__global__ __launch_bounds__(256)
void gemm_batched(GemmBatch args) {
    constexpr int MT = 4;
    constexpr uint32_t ABYTES = 128 * 80;
    constexpr uint32_t BBYTES = 128 * 80;
    constexpr uint32_t STG    = 2 * ABYTES + 2 * BBYTES;
    extern __shared__ char smem[];
    const uint32_t sb = smem_u32(smem);

    int id = blockIdx.x, s = 0;
#pragma unroll
    for (int i = 0; i < 3; i++) {
        bool adv = (id >= args.cnt[s]);
        if (adv) { id -= args.cnt[s]; s++; }
    }
    const __half* Ah = args.Ah[s];
    const __half* Al = args.Al[s];
    const __half* Bh = args.Bh[s];
    const __half* Bl = args.Bl[s];
    float* C0 = args.C0[s];
    float* C1 = args.C1[s];
    __half* Ho = args.Ho[s];
    const int nbx = args.nbx[s];
    const int bx = id % nbx, by = id / nbx;
    const int m0 = by * 128, n0 = bx * 128;

    const int tid = threadIdx.x;
    const int wid = tid >> 5, lane = tid & 31;
    const int wm = wid >> 2, wn = wid & 3;

    const uint32_t rowA = (uint32_t)(wm * 64 + (lane & 7) + ((lane >> 3) & 1) * 8);
    const uint32_t colA = (uint32_t)(((lane >> 4) & 1) * 16);
    const uint32_t oAh = rowA * 80 + colA;
    const uint32_t oAl = oAh + ABYTES;
    const uint32_t rowB = (uint32_t)(wn * 32 + (lane & 7));
    const uint32_t colB = (uint32_t)(((lane >> 3) & 1) * 16);
    const uint32_t oBh = 2 * ABYTES + rowB * 80 + colB;
    const uint32_t oBl = oBh + BBYTES;

    float acc[MT][4][4];
#pragma unroll
    for (int i = 0; i < MT; i++)
#pragma unroll
        for (int j = 0; j < 4; j++)
#pragma unroll
            for (int e = 0; e < 4; e++) acc[i][j][e] = 0.f;

    auto load_stage = [&](int st, int kc) {
        const int k0 = kc * 32;
        const uint32_t base = sb + st * STG;
#pragma unroll
        for (int i = 0; i < 2; i++) {
            int c = tid + i * 256;
            int r = c >> 2, qq = c & 3;
            uint32_t dst = base + r * 80 + qq * 16;
            const size_t ga = (size_t)(m0 + r) * 512 + k0 + qq * 8;
            cp16(dst, Ah + ga);
            if (Al) cp16(dst + ABYTES, Al + ga);
            uint32_t dstB = base + 2 * ABYTES + r * 80 + qq * 16;
            const size_t gb = (size_t)(n0 + r) * 512 + k0 + qq * 8;
            cp16(dstB, Bh + gb);
            if (Bl) cp16(dstB + BBYTES, Bl + gb);
        }
    };

    load_stage(0, 0); CP_COMMIT();
    load_stage(1, 1); CP_COMMIT();

    for (int kc = 0; kc < 16; kc++) {
        if (kc < 15) { CP_WAIT1(); } else { CP_WAIT0(); }
        __syncthreads();
        const uint32_t so = sb + (kc & 1) * STG;
#pragma unroll
        for (int ks = 0; ks < 2; ks++) {
            uint32_t bh[4][2], bl[4][2];
#pragma unroll
            for (int ni = 0; ni < 4; ni++) ldsm_x2(bh[ni], so + oBh + ni * 640 + ks * 32);
            if (Bl) {
#pragma unroll
                for (int ni = 0; ni < 4; ni++) ldsm_x2(bl[ni], so + oBl + ni * 640 + ks * 32);
            }
#pragma unroll
            for (int mi = 0; mi < MT; mi++) {
                uint32_t ah[4];
                ldsm_x4(ah, so + oAh + mi * 1280 + ks * 32);
#pragma unroll
                for (int ni = 0; ni < 4; ni++) mma16816(acc[mi][ni], ah, bh[ni]);
                if (Bl) {
#pragma unroll
                    for (int ni = 0; ni < 4; ni++) mma16816(acc[mi][ni], ah, bl[ni]);
                }
                if (Al) {
                    uint32_t al[4];
                    ldsm_x4(al, so + oAl + mi * 1280 + ks * 32);
#pragma unroll
                    for (int ni = 0; ni < 4; ni++) mma16816(acc[mi][ni], al, bh[ni]);
                }
            }
        }
        __syncthreads();
        if (kc + 2 < 16) { load_stage(kc & 1, kc + 2); }
        CP_COMMIT();
    }

    const int mrow = m0 + wm * 64 + (lane >> 2);
    const int ncol = n0 + wn * 32 + (lane & 3) * 2;
#pragma unroll
    for (int mi = 0; mi < MT; mi++) {
#pragma unroll
        for (int ni = 0; ni < 4; ni++) {
            int col = ncol + ni * 8;
            int r0 = mrow + mi * 16;
            if (Ho) {
                *(__half2*)&Ho[(size_t)r0 * 512 + col] =
                    __floats2half2_rn(acc[mi][ni][0], acc[mi][ni][1]);
                *(__half2*)&Ho[(size_t)(r0 + 8) * 512 + col] =
                    __floats2half2_rn(acc[mi][ni][2], acc[mi][ni][3]);
            } else {
                float* dst = (C1 && col >= 512) ? (C1 + col - 512) : (C0 + col);
                *(float2*)&dst[(size_t)r0 * 512]       = make_float2(acc[mi][ni][0], acc[mi][ni][1]);
                *(float2*)&dst[(size_t)(r0 + 8) * 512] = make_float2(acc[mi][ni][2], acc[mi][ni][3]);
            }
        }
    }
}

// ---------------------------------------------------------------------------
// Hierarchical attention v2: block per (b,h,q-half). fp16 output (hi only).
// ---------------------------------------------------------------------------
#define ATTN_SMEM 195584

__global__ __launch_bounds__(512)
void attn2(const int* __restrict__ valid_lens) {
    extern __shared__ char sm[];
    __half* kv   = (__half*)sm;                                 // [1024][66]
    float*  ks_t = (float*)(sm + 135168);                       // [64][68]
    float*  qs   = (float*)(sm + 135168 + 17408);               // [32][64]
    float*  qt   = qs + 2048;
    float*  sc   = qt + 2048;
    float*  cw   = sc + 2048;                                   // [32][128]
    int*    sidx = (int*)(cw + 4096);                           // [32][8]
    float*  sw8  = (float*)(sidx + 256);                        // [32][8]

    const int bh = blockIdx.x;
    const int b = bh >> 3, h = bh & 7;
    const int qh = blockIdx.y;
    const int qbase = b * 64 + qh * 32;
    const int tid = threadIdx.x, wid = tid >> 5, lane = tid & 31;
    const float scale = 0.125f;

#pragma unroll
    for (int k = 0; k < 2; k++) {
        int i4 = tid + k * 512;
        int s = i4 >> 4, dq = i4 & 15;
        float4 v = *(const float4*)&g_k_stat[(size_t)(b * 64 + s) * 512 + h * 64 + dq * 4];
        ks_t[(dq * 4 + 0) * 68 + s] = v.x;
        ks_t[(dq * 4 + 1) * 68 + s] = v.y;
        ks_t[(dq * 4 + 2) * 68 + s] = v.z;
        ks_t[(dq * 4 + 3) * 68 + s] = v.w;
    }
    {
        int q = tid >> 4, dq = tid & 15;
        *(float4*)&qs[q * 64 + dq * 4] =
            *(const float4*)&g_q_stat[(size_t)(qbase + q) * 512 + h * 64 + dq * 4];
        *(float4*)&qt[q * 64 + dq * 4] =
            *(const float4*)&g_q_tok[(size_t)(qbase + q) * 512 + h * 64 + dq * 4];
    }
#pragma unroll
    for (int k = 0; k < 16; k++) {
        int idx = tid + k * 512;
        int r = idx >> 3, c = idx & 7;
        uint4 v = *(const uint4*)&g_ktk16[((size_t)(b * 1024) + r) * 512 + h * 64 + c * 8];
        uint32_t* dst = (uint32_t*)kv + r * 33 + c * 4;
        dst[0] = v.x; dst[1] = v.y; dst[2] = v.z; dst[3] = v.w;
    }
    __syncthreads();

    const int vlen = valid_lens[b];

    {
        const int q = tid >> 4, sg = tid & 15;
        float a0 = 0.f, a1 = 0.f, a2 = 0.f, a3 = 0.f;
        const float* qrow = &qs[q * 64];
#pragma unroll
        for (int d = 0; d < 64; d++) {
            float qv = qrow[d];
            float4 kf = *(const float4*)&ks_t[d * 68 + sg * 4];
            a0 = fmaf(qv, kf.x, a0);
            a1 = fmaf(qv, kf.y, a1);
            a2 = fmaf(qv, kf.z, a2);
            a3 = fmaf(qv, kf.w, a3);
        }
        const int s0 = sg * 4;
        sc[q * 64 + s0 + 0] = (s0 + 0 < vlen) ? a0 * scale : NEGV;
        sc[q * 64 + s0 + 1] = (s0 + 1 < vlen) ? a1 * scale : NEGV;
        sc[q * 64 + s0 + 2] = (s0 + 2 < vlen) ? a2 * scale : NEGV;
        sc[q * 64 + s0 + 3] = (s0 + 3 < vlen) ? a3 * scale : NEGV;
    }
    __syncthreads();

    for (int rep = 0; rep < 2; rep++) {
        const int q = wid * 2 + rep;
        float v0 = sc[q * 64 + lane], v1 = sc[q * 64 + lane + 32];
        int i0 = lane, i1 = lane + 32;
        float vals[8];
#pragma unroll
        for (int j = 0; j < 8; j++) {
            float m; int mi;
            if (v0 >= v1) { m = v0; mi = i0; } else { m = v1; mi = i1; }
#pragma unroll
            for (int o = 16; o; o >>= 1) {
                float om = __shfl_xor_sync(~0u, m, o);
                int   oi = __shfl_xor_sync(~0u, mi, o);
                if (om > m || (om == m && oi < mi)) { m = om; mi = oi; }
            }
            if (lane == 0) { sidx[q * 8 + j] = mi; vals[j] = m; }
            if (i0 == mi) v0 = -3.0e38f;
            if (i1 == mi) v1 = -3.0e38f;
        }
        if (lane == 0) {
            const float m = vals[0];
            float e[8], sum = 0.f;
#pragma unroll
            for (int j = 0; j < 8; j++) { e[j] = expf(vals[j] - m); sum += e[j]; }
            const float inv = 1.f / sum;
#pragma unroll
            for (int j = 0; j < 8; j++) sw8[q * 8 + j] = e[j] * inv;
        }
    }
    __syncthreads();

    {
        const int t = lane >> 1, hf = lane & 1;
        for (int kk = 0; kk < 16; kk++) {
            const int q = wid * 2 + (kk >> 3);
            const int j = kk & 7;
            const int row = sidx[q * 8 + j] * 16 + t;
            const uint32_t* kr = (const uint32_t*)kv + row * 33 + hf * 16;
            const float* qr = &qt[q * 64 + hf * 32];
            float acc = 0.f;
#pragma unroll
            for (int it = 0; it < 16; it++) {
                float2 kf = __half22float2(*(const __half2*)&kr[it]);
                float2 q2 = *(const float2*)&qr[it * 2];
                acc = fmaf(q2.x, kf.x, acc);
                acc = fmaf(q2.y, kf.y, acc);
            }
            acc += __shfl_xor_sync(~0u, acc, 1);
            if (hf == 0) cw[q * 128 + j * 16 + t] = acc * scale;
        }
    }
    __syncthreads();

#pragma unroll
    for (int k = 0; k < 16; k++) {
        int idx = tid + k * 512;
        int r = idx >> 3, c = idx & 7;
        uint4 v = *(const uint4*)&g_v16h[((size_t)(b * 1024) + r) * 512 + h * 64 + c * 8];
        uint32_t* dst = (uint32_t*)kv + r * 33 + c * 4;
        dst[0] = v.x; dst[1] = v.y; dst[2] = v.z; dst[3] = v.w;
    }
    if (tid < 256) {
        const int q = tid >> 3, j = tid & 7;
        float* c = &cw[q * 128 + j * 16];
        float m = c[0];
#pragma unroll
        for (int t = 1; t < 16; t++) m = fmaxf(m, c[t]);
        float e[16], sum = 0.f;
#pragma unroll
        for (int t = 0; t < 16; t++) { e[t] = expf(c[t] - m); sum += e[t]; }
        const float f = sw8[q * 8 + j] / sum;
#pragma unroll
        for (int t = 0; t < 16; t++) c[t] = e[t] * f;
    }
    __syncthreads();

    {
        const int q = tid >> 4, dg = tid & 15;
        float a0 = 0.f, a1 = 0.f, b0 = 0.f, b1 = 0.f;
#pragma unroll
        for (int j = 0; j < 8; j++) {
            const int rbase = sidx[q * 8 + j] * 16;
            const float* cwr = &cw[q * 128 + j * 16];
#pragma unroll
            for (int t = 0; t < 16; t++) {
                const float w = cwr[t];
                const uint32_t* vr = (const uint32_t*)kv + (rbase + t) * 33;
                float2 va = __half22float2(*(const __half2*)&vr[dg]);
                float2 vb = __half22float2(*(const __half2*)&vr[dg + 16]);
                a0 = fmaf(w, va.x, a0);
                a1 = fmaf(w, va.y, a1);
                b0 = fmaf(w, vb.x, b0);
                b1 = fmaf(w, vb.y, b1);
            }
        }
        const size_t off = (size_t)(qbase + q) * 512 + h * 64;
        *(__half2*)&g_at_h[off + 2 * dg]      = __floats2half2_rn(a0, a1);
        *(__half2*)&g_at_h[off + 32 + 2 * dg] = __floats2half2_rn(b0, b1);
    }
}

// ---------------------------------------------------------------------------
extern "C" void kernel_launch(void* const* d_in, const int* in_sizes, int n_in,
                              void* d_out, int out_size) {
    const float* queries        = (const float*)d_in[0];
    const float* stat_keys      = (const float*)d_in[1];
    const float* token_keys     = (const float*)d_in[2];
    const float* values         = (const float*)d_in[3];
    const int*   stat_valid_len = (const int*)  d_in[4];
    WPtrs ws;
    for (int i = 0; i < 6; i++) ws.p[i] = (const float*)d_in[5 + i];
    float* out = (float*)d_out;

    __half *cq_h, *cq_l, *csk_h, *csk_l, *ctk_h, *cv_h;
    __half *wh, *wl, *at_h, *ktk16, *v16h;
    float *q_stat, *q_tok, *k_stat;
    cudaGetSymbolAddress((void**)&cq_h,  g_cq_h);  cudaGetSymbolAddress((void**)&cq_l,  g_cq_l);
    cudaGetSymbolAddress((void**)&csk_h, g_csk_h); cudaGetSymbolAddress((void**)&csk_l, g_csk_l);
    cudaGetSymbolAddress((void**)&ctk_h, g_ctk_h); cudaGetSymbolAddress((void**)&cv_h,  g_cv_h);
    cudaGetSymbolAddress((void**)&wh,    g_wh);    cudaGetSymbolAddress((void**)&wl,    g_wl);
    cudaGetSymbolAddress((void**)&at_h,  g_at_h);
    cudaGetSymbolAddress((void**)&ktk16, g_ktk16); cudaGetSymbolAddress((void**)&v16h,  g_v16h);
    cudaGetSymbolAddress((void**)&q_stat, g_q_stat);
    cudaGetSymbolAddress((void**)&q_tok,  g_q_tok);
    cudaGetSymbolAddress((void**)&k_stat, g_k_stat);

    const size_t WSZ = (size_t)512 * 512;
    constexpr int SMEM = 2 * (2 * 128 * 80 + 2 * 128 * 80);  // 81920
    cudaFuncSetAttribute(gemm_batched, cudaFuncAttributeMaxDynamicSharedMemorySize, SMEM);
    cudaFuncSetAttribute(attn2, cudaFuncAttributeMaxDynamicSharedMemorySize, ATTN_SMEM);

    // 1) fused prep: weights (1536 blocks) + input conversion (8704 blocks)
    prep_all<<<10240, 256>>>(ws, queries, stat_keys, token_keys, values);

    // 2) all five projections in one launch (560 CTAs)
    GemmBatch gb;
    // seg 0: queries @ [Wq_stat|Wq_token] (3-term, fp32 split out)
    gb.Ah[0] = cq_h;  gb.Al[0] = cq_l;  gb.Bh[0] = wh;           gb.Bl[0] = wl;
    gb.C0[0] = q_stat; gb.C1[0] = q_tok; gb.Ho[0] = nullptr; gb.nbx[0] = 8; gb.cnt[0] = 32;
    // seg 1: stat_keys @ Wk_stat (3-term, fp32 out)
    gb.Ah[1] = csk_h; gb.Al[1] = csk_l; gb.Bh[1] = wh + 2 * WSZ; gb.Bl[1] = wl + 2 * WSZ;
    gb.C0[1] = k_stat; gb.C1[1] = nullptr; gb.Ho[1] = nullptr; gb.nbx[1] = 4; gb.cnt[1] = 16;
    // seg 2: token_keys16 @ Wk_token (1-term, fp16 out)
    gb.Ah[2] = ctk_h; gb.Al[2] = nullptr; gb.Bh[2] = wh + 3 * WSZ; gb.Bl[2] = nullptr;
    gb.C0[2] = nullptr; gb.C1[2] = nullptr; gb.Ho[2] = ktk16; gb.nbx[2] = 4; gb.cnt[2] = 256;
    // seg 3: values16 @ Wv (1-term, fp16 out)
    gb.Ah[3] = cv_h;  gb.Al[3] = nullptr; gb.Bh[3] = wh + 4 * WSZ; gb.Bl[3] = nullptr;
    gb.C0[3] = nullptr; gb.C1[3] = nullptr; gb.Ho[3] = v16h; gb.nbx[3] = 4; gb.cnt[3] = 256;
    gemm_batched<<<560, 256, SMEM>>>(gb);

    // 3) attention v2
    attn2<<<dim3(64, 2), 512, ATTN_SMEM>>>(stat_valid_len);

    // 4) output projection (2-term, fp32 out)
    GemmBatch go;
    go.Ah[0] = at_h; go.Al[0] = nullptr; go.Bh[0] = wh + 5 * WSZ; go.Bl[0] = wl + 5 * WSZ;
    go.C0[0] = out;  go.C1[0] = nullptr; go.Ho[0] = nullptr; go.nbx[0] = 4; go.cnt[0] = 16;
    go.cnt[1] = go.cnt[2] = go.cnt[3] = 0x7fffffff;
    go.Ah[1] = go.Ah[2] = go.Ah[3] = at_h; go.Al[1] = go.Al[2] = go.Al[3] = nullptr;
    go.Bh[1] = go.Bh[2] = go.Bh[3] = wh;   go.Bl[1] = go.Bl[2] = go.Bl[3] = wl;
    go.C0[1] = go.C0[2] = go.C0[3] = out;  go.C1[1] = go.C1[2] = go.C1[3] = nullptr;
    go.Ho[1] = go.Ho[2] = go.Ho[3] = nullptr;
    go.nbx[1] = go.nbx[2] = go.nbx[3] = 4;
    gemm_batched<<<16, 256, SMEM>>>(go);
}

// round 14
// speedup vs baseline: 1.3821x; 1.1080x over previous
#include <cuda_runtime.h>
#include <cuda_fp16.h>
#include <cstdint>
#include <math.h>

#define B_   8
#define Q_   64
#define S_   64
#define T_   64
#define H_   8
#define DH_  64
#define NH_  512
#define NEGV (-1e6f)

// ---------------------------------------------------------------------------
// Scratch (device globals)
// ---------------------------------------------------------------------------
__device__ __half g_cq_h [512 * 512],  g_cq_l [512 * 512];    // queries hi/lo
__device__ __half g_csk_h[512 * 512],  g_csk_l[512 * 512];    // stat_keys hi/lo
__device__ __half g_ctk_h[8192 * 512];                        // gathered token_keys fp16
__device__ __half g_cv_h [8192 * 512];                        // gathered values fp16
__device__ __half g_wh[6 * 512 * 512], g_wl[6 * 512 * 512];   // W^T [N,K] fp16 hi/lo
__device__ float g_q_stat[512 * 512];
__device__ float g_q_tok [512 * 512];
__device__ float g_k_stat[512 * 512];
__device__ __half g_ktk16[8192 * 512];                        // projected token keys (fp16)
__device__ __half g_v16h [8192 * 512];                        // projected values (fp16)
__device__ __half g_at_h[512 * 512];                          // attn out fp16

// ---------------------------------------------------------------------------
// helpers
// ---------------------------------------------------------------------------
__device__ __forceinline__ uint32_t smem_u32(const void* p) {
    uint32_t a;
    asm("{ .reg .u64 t; cvta.to.shared.u64 t, %1; cvt.u32.u64 %0, t; }" : "=r"(a) : "l"(p));
    return a;
}
__device__ __forceinline__ void ldsm_x4(uint32_t* r, uint32_t addr) {
    asm volatile("ldmatrix.sync.aligned.m8n8.x4.shared.b16 {%0,%1,%2,%3}, [%4];"
        : "=r"(r[0]), "=r"(r[1]), "=r"(r[2]), "=r"(r[3]) : "r"(addr));
}
__device__ __forceinline__ void ldsm_x2(uint32_t* r, uint32_t addr) {
    asm volatile("ldmatrix.sync.aligned.m8n8.x2.shared.b16 {%0,%1}, [%2];"
        : "=r"(r[0]), "=r"(r[1]) : "r"(addr));
}
__device__ __forceinline__ void mma16816(float* d, const uint32_t* a, const uint32_t* b) {
    asm volatile("mma.sync.aligned.m16n8k16.row.col.f32.f16.f16.f32 "
        "{%0,%1,%2,%3}, {%4,%5,%6,%7}, {%8,%9}, {%0,%1,%2,%3};"
        : "+f"(d[0]), "+f"(d[1]), "+f"(d[2]), "+f"(d[3])
        : "r"(a[0]), "r"(a[1]), "r"(a[2]), "r"(a[3]), "r"(b[0]), "r"(b[1]));
}
__device__ __forceinline__ void cp16(uint32_t dst, const void* src) {
    asm volatile("cp.async.cg.shared.global [%0], [%1], 16;" :: "r"(dst), "l"(src));
}
#define CP_COMMIT() asm volatile("cp.async.commit_group;" ::: "memory")
#define CP_WAIT2()  asm volatile("cp.async.wait_group 2;" ::: "memory")
#define CP_WAIT1()  asm volatile("cp.async.wait_group 1;" ::: "memory")
#define CP_WAIT0()  asm volatile("cp.async.wait_group 0;" ::: "memory")

__device__ __forceinline__ uint32_t pack2h(float a, float b) {
    return (uint32_t)__half_as_ushort(__float2half(a)) |
           ((uint32_t)__half_as_ushort(__float2half(b)) << 16);
}

// ---------------------------------------------------------------------------
// Fused prep: weight transpose+split (blocks [0,1536)) and input conversion
// (blocks [1536,10240)) in ONE launch.
// ---------------------------------------------------------------------------
struct WPtrs { const float* p[6]; };

__global__ __launch_bounds__(256)
void prep_all(WPtrs ws, const float* __restrict__ q, const float* __restrict__ sk,
              const float* __restrict__ tk, const float* __restrict__ v) {
    __shared__ float t[32][33];
    const int bid = blockIdx.x;
    const int tid = threadIdx.x;

    if (bid < 1536) {
        const int widx = bid / 256;
        const int rem = bid % 256;
        const int n0 = (rem & 15) * 32, k0 = (rem >> 4) * 32;
        const float* W = ws.p[widx];
        __half* hiw = g_wh + (size_t)widx * 512 * 512;
        __half* low = g_wl + (size_t)widx * 512 * 512;
        const int tx = tid & 31, ty = tid >> 5;
#pragma unroll
        for (int i = ty; i < 32; i += 8)
            t[i][tx] = W[(size_t)(k0 + i) * 512 + n0 + tx];
        __syncthreads();
#pragma unroll
        for (int i = ty; i < 32; i += 8) {
            float val = t[tx][i];
            __half h = __float2half(val);
            hiw[(size_t)(n0 + i) * 512 + k0 + tx] = h;
            low[(size_t)(n0 + i) * 512 + k0 + tx] = __float2half(val - __half2float(h));
        }
        return;
    }

    const int cid = bid - 1536;
    int z, base;
    if (cid < 256)       { z = 0; base = cid; }
    else if (cid < 512)  { z = 1; base = cid - 256; }
    else if (cid < 4608) { z = 2; base = cid - 512; }
    else                 { z = 3; base = cid - 4608; }
    const int idx = base * 256 + tid;
    const int r = idx >> 7, c4 = idx & 127;

    if (z < 2) {
        const float* src = z ? sk : q;
        __half* dh = z ? g_csk_h : g_cq_h;
        __half* dl = z ? g_csk_l : g_cq_l;
        float4 x = *(const float4*)&src[(size_t)r * 512 + c4 * 4];
        __half h0 = __float2half(x.x), h1 = __float2half(x.y),
               h2 = __float2half(x.z), h3 = __float2half(x.w);
        uint2 hh, ll;
        hh.x = (uint32_t)__half_as_ushort(h0) | ((uint32_t)__half_as_ushort(h1) << 16);
        hh.y = (uint32_t)__half_as_ushort(h2) | ((uint32_t)__half_as_ushort(h3) << 16);
        ll.x = pack2h(x.x - __half2float(h0), x.y - __half2float(h1));
        ll.y = pack2h(x.z - __half2float(h2), x.w - __half2float(h3));
        *(uint2*)&dh[(size_t)r * 512 + c4 * 4] = hh;
        *(uint2*)&dl[(size_t)r * 512 + c4 * 4] = ll;
    } else {
        const int sr = (r >> 4) * 64 + 48 + (r & 15);
        const float* src = (z == 2) ? tk : v;
        __half* dh = (z == 2) ? g_ctk_h : g_cv_h;
        float4 x = *(const float4*)&src[(size_t)sr * 512 + c4 * 4];
        uint2 hh;
        hh.x = pack2h(x.x, x.y);
        hh.y = pack2h(x.z, x.w);
        *(uint2*)&dh[(size_t)r * 512 + c4 * 4] = hh;
    }
}

// ---------------------------------------------------------------------------
// Batched fp16 hi/lo GEMM (128x128 tiles), cp.async 2-stage pipeline.
// ---------------------------------------------------------------------------
struct GemmBatch {
    const __half *Ah[4], *Al[4], *Bh[4], *Bl[4];
    float *C0[4], *C1[4];
    __half *Ho[4];
    int nbx[4];
    int cnt[4];
};

__global__ __launch_bounds__(256)
void gemm_batched(GemmBatch args) {
    constexpr int MT = 4;
    constexpr uint32_t ABYTES = 128 * 80;
    constexpr uint32_t BBYTES = 128 * 80;
    constexpr uint32_t STG    = 2 * ABYTES + 2 * BBYTES;
    extern __shared__ char smem[];
    const uint32_t sb = smem_u32(smem);

    int id = blockIdx.x, s = 0;
#pragma unroll
    for (int i = 0; i < 3; i++) {
        bool adv = (id >= args.cnt[s]);
        if (adv) { id -= args.cnt[s]; s++; }
    }
    const __half* Ah = args.Ah[s];
    const __half* Al = args.Al[s];
    const __half* Bh = args.Bh[s];
    const __half* Bl = args.Bl[s];
    float* C0 = args.C0[s];
    float* C1 = args.C1[s];
    __half* Ho = args.Ho[s];
    const int nbx = args.nbx[s];
    const int bx = id % nbx, by = id / nbx;
    const int m0 = by * 128, n0 = bx * 128;

    const int tid = threadIdx.x;
    const int wid = tid >> 5, lane = tid & 31;
    const int wm = wid >> 2, wn = wid & 3;

    const uint32_t rowA = (uint32_t)(wm * 64 + (lane & 7) + ((lane >> 3) & 1) * 8);
    const uint32_t colA = (uint32_t)(((lane >> 4) & 1) * 16);
    const uint32_t oAh = rowA * 80 + colA;
    const uint32_t oAl = oAh + ABYTES;
    const uint32_t rowB = (uint32_t)(wn * 32 + (lane & 7));
    const uint32_t colB = (uint32_t)(((lane >> 3) & 1) * 16);
    const uint32_t oBh = 2 * ABYTES + rowB * 80 + colB;
    const uint32_t oBl = oBh + BBYTES;

    float acc[MT][4][4];
#pragma unroll
    for (int i = 0; i < MT; i++)
#pragma unroll
        for (int j = 0; j < 4; j++)
#pragma unroll
            for (int e = 0; e < 4; e++) acc[i][j][e] = 0.f;

    auto load_stage = [&](int st, int kc) {
        const int k0 = kc * 32;
        const uint32_t base = sb + st * STG;
#pragma unroll
        for (int i = 0; i < 2; i++) {
            int c = tid + i * 256;
            int r = c >> 2, qq = c & 3;
            uint32_t dst = base + r * 80 + qq * 16;
            const size_t ga = (size_t)(m0 + r) * 512 + k0 + qq * 8;
            cp16(dst, Ah + ga);
            if (Al) cp16(dst + ABYTES, Al + ga);
            uint32_t dstB = base + 2 * ABYTES + r * 80 + qq * 16;
            const size_t gb = (size_t)(n0 + r) * 512 + k0 + qq * 8;
            cp16(dstB, Bh + gb);
            if (Bl) cp16(dstB + BBYTES, Bl + gb);
        }
    };

    load_stage(0, 0); CP_COMMIT();
    load_stage(1, 1); CP_COMMIT();

    for (int kc = 0; kc < 16; kc++) {
        if (kc < 15) { CP_WAIT1(); } else { CP_WAIT0(); }
        __syncthreads();
        const uint32_t so = sb + (kc & 1) * STG;
#pragma unroll
        for (int ks = 0; ks < 2; ks++) {
            uint32_t bh[4][2], bl[4][2];
#pragma unroll
            for (int ni = 0; ni < 4; ni++) ldsm_x2(bh[ni], so + oBh + ni * 640 + ks * 32);
            if (Bl) {
#pragma unroll
                for (int ni = 0; ni < 4; ni++) ldsm_x2(bl[ni], so + oBl + ni * 640 + ks * 32);
            }
#pragma unroll
            for (int mi = 0; mi < MT; mi++) {
                uint32_t ah[4];
                ldsm_x4(ah, so + oAh + mi * 1280 + ks * 32);
#pragma unroll
                for (int ni = 0; ni < 4; ni++) mma16816(acc[mi][ni], ah, bh[ni]);
                if (Bl) {
#pragma unroll
                    for (int ni = 0; ni < 4; ni++) mma16816(acc[mi][ni], ah, bl[ni]);
                }
                if (Al) {
                    uint32_t al[4];
                    ldsm_x4(al, so + oAl + mi * 1280 + ks * 32);
#pragma unroll
                    for (int ni = 0; ni < 4; ni++) mma16816(acc[mi][ni], al, bh[ni]);
                }
            }
        }
        __syncthreads();
        if (kc + 2 < 16) { load_stage(kc & 1, kc + 2); }
        CP_COMMIT();
    }

    const int mrow = m0 + wm * 64 + (lane >> 2);
    const int ncol = n0 + wn * 32 + (lane & 3) * 2;
#pragma unroll
    for (int mi = 0; mi < MT; mi++) {
#pragma unroll
        for (int ni = 0; ni < 4; ni++) {
            int col = ncol + ni * 8;
            int r0 = mrow + mi * 16;
            if (Ho) {
                *(__half2*)&Ho[(size_t)r0 * 512 + col] =
                    __floats2half2_rn(acc[mi][ni][0], acc[mi][ni][1]);
                *(__half2*)&Ho[(size_t)(r0 + 8) * 512 + col] =
                    __floats2half2_rn(acc[mi][ni][2], acc[mi][ni][3]);
            } else {
                float* dst = (C1 && col >= 512) ? (C1 + col - 512) : (C0 + col);
                *(float2*)&dst[(size_t)r0 * 512]       = make_float2(acc[mi][ni][0], acc[mi][ni][1]);
                *(float2*)&dst[(size_t)(r0 + 8) * 512] = make_float2(acc[mi][ni][2], acc[mi][ni][3]);
            }
        }
    }
}

// ---------------------------------------------------------------------------
// Small GEMM for Wo: C[512,512] = A(fp16) @ B(fp16 hi/lo)^T, 2-term.
// 64x64 tiles -> 64 CTAs; 128 threads (2x2 warps, 32x32 warp tile);
// 4-stage cp.async pipeline (3 chunks in flight) to hide L2 latency.
// ---------------------------------------------------------------------------
__global__ __launch_bounds__(128)
void gemm_wo(const __half* __restrict__ Ah, const __half* __restrict__ Bh,
             const __half* __restrict__ Bl, float* __restrict__ C) {
    constexpr uint32_t ABYTES = 64 * 80;       // 5120
    constexpr uint32_t BBYTES = 64 * 80;
    constexpr uint32_t STG    = ABYTES + 2 * BBYTES;   // 15360
    extern __shared__ char smem[];
    const uint32_t sb = smem_u32(smem);

    const int tid = threadIdx.x;
    const int wid = tid >> 5, lane = tid & 31;
    const int wm = wid >> 1, wn = wid & 1;
    const int m0 = blockIdx.y * 64, n0 = blockIdx.x * 64;

    const uint32_t rowA = (uint32_t)(wm * 32 + (lane & 7) + ((lane >> 3) & 1) * 8);
    const uint32_t colA = (uint32_t)(((lane >> 4) & 1) * 16);
    const uint32_t oAh = rowA * 80 + colA;
    const uint32_t rowB = (uint32_t)(wn * 32 + (lane & 7));
    const uint32_t colB = (uint32_t)(((lane >> 3) & 1) * 16);
    const uint32_t oBh = ABYTES + rowB * 80 + colB;
    const uint32_t oBl = oBh + BBYTES;

    float acc[2][4][4];
#pragma unroll
    for (int i = 0; i < 2; i++)
#pragma unroll
        for (int j = 0; j < 4; j++)
#pragma unroll
            for (int e = 0; e < 4; e++) acc[i][j][e] = 0.f;

    auto load_stage = [&](int st, int kc) {
        const int k0 = kc * 32;
        const uint32_t base = sb + st * STG;
#pragma unroll
        for (int i = 0; i < 2; i++) {
            int c = tid + i * 128;
            int r = c >> 2, qq = c & 3;
            uint32_t dst = base + r * 80 + qq * 16;
            cp16(dst, Ah + (size_t)(m0 + r) * 512 + k0 + qq * 8);
            uint32_t dstB = base + ABYTES + r * 80 + qq * 16;
            const size_t gb = (size_t)(n0 + r) * 512 + k0 + qq * 8;
            cp16(dstB, Bh + gb);
            cp16(dstB + BBYTES, Bl + gb);
        }
    };

    load_stage(0, 0); CP_COMMIT();
    load_stage(1, 1); CP_COMMIT();
    load_stage(2, 2); CP_COMMIT();

    for (int kc = 0; kc < 16; kc++) {
        if (kc <= 13) { CP_WAIT2(); }
        else if (kc == 14) { CP_WAIT1(); }
        else { CP_WAIT0(); }
        __syncthreads();
        const uint32_t so = sb + (kc & 3) * STG;
#pragma unroll
        for (int ks = 0; ks < 2; ks++) {
            uint32_t bh[4][2], bl[4][2];
#pragma unroll
            for (int ni = 0; ni < 4; ni++) ldsm_x2(bh[ni], so + oBh + ni * 640 + ks * 32);
#pragma unroll
            for (int ni = 0; ni < 4; ni++) ldsm_x2(bl[ni], so + oBl + ni * 640 + ks * 32);
#pragma unroll
            for (int mi = 0; mi < 2; mi++) {
                uint32_t ah[4];
                ldsm_x4(ah, so + oAh + mi * 1280 + ks * 32);
#pragma unroll
                for (int ni = 0; ni < 4; ni++) mma16816(acc[mi][ni], ah, bh[ni]);
#pragma unroll
                for (int ni = 0; ni < 4; ni++) mma16816(acc[mi][ni], ah, bl[ni]);
            }
        }
        if (kc + 3 < 16) { load_stage((kc + 3) & 3, kc + 3); CP_COMMIT(); }
    }

    const int mrow = m0 + wm * 32 + (lane >> 2);
    const int ncol = n0 + wn * 32 + (lane & 3) * 2;
#pragma unroll
    for (int mi = 0; mi < 2; mi++) {
#pragma unroll
        for (int ni = 0; ni < 4; ni++) {
            int col = ncol + ni * 8;
            int r0 = mrow + mi * 16;
            *(float2*)&C[(size_t)r0 * 512 + col]       = make_float2(acc[mi][ni][0], acc[mi][ni][1]);
            *(float2*)&C[(size_t)(r0 + 8) * 512 + col] = make_float2(acc[mi][ni][2], acc[mi][ni][3]);
        }
    }
}

// ---------------------------------------------------------------------------
// Hierarchical attention v2: block per (b,h,q-half). fp16 output (hi only).
// ---------------------------------------------------------------------------
#define ATTN_SMEM 195584

__global__ __launch_bounds__(512)
void attn2(const int* __restrict__ valid_lens) {
    extern __shared__ char sm[];
    __half* kv   = (__half*)sm;                                 // [1024][66]
    float*  ks_t = (float*)(sm + 135168);                       // [64][68]
    float*  qs   = (float*)(sm + 135168 + 17408);               // [32][64]
    float*  qt   = qs + 2048;
    float*  sc   = qt + 2048;
    float*  cw   = sc + 2048;                                   // [32][128]
    int*    sidx = (int*)(cw + 4096);                           // [32][8]
    float*  sw8  = (float*)(sidx + 256);                        // [32][8]

    const int bh = blockIdx.x;
    const int b = bh >> 3, h = bh & 7;
    const int qh = blockIdx.y;
    const int qbase = b * 64 + qh * 32;
    const int tid = threadIdx.x, wid = tid >> 5, lane = tid & 31;
    const float scale = 0.125f;

#pragma unroll
    for (int k = 0; k < 2; k++) {
        int i4 = tid + k * 512;
        int s = i4 >> 4, dq = i4 & 15;
        float4 v = *(const float4*)&g_k_stat[(size_t)(b * 64 + s) * 512 + h * 64 + dq * 4];
        ks_t[(dq * 4 + 0) * 68 + s] = v.x;
        ks_t[(dq * 4 + 1) * 68 + s] = v.y;
        ks_t[(dq * 4 + 2) * 68 + s] = v.z;
        ks_t[(dq * 4 + 3) * 68 + s] = v.w;
    }
    {
        int q = tid >> 4, dq = tid & 15;
        *(float4*)&qs[q * 64 + dq * 4] =
            *(const float4*)&g_q_stat[(size_t)(qbase + q) * 512 + h * 64 + dq * 4];
        *(float4*)&qt[q * 64 + dq * 4] =
            *(const float4*)&g_q_tok[(size_t)(qbase + q) * 512 + h * 64 + dq * 4];
    }
#pragma unroll
    for (int k = 0; k < 16; k++) {
        int idx = tid + k * 512;
        int r = idx >> 3, c = idx & 7;
        uint4 v = *(const uint4*)&g_ktk16[((size_t)(b * 1024) + r) * 512 + h * 64 + c * 8];
        uint32_t* dst = (uint32_t*)kv + r * 33 + c * 4;
        dst[0] = v.x; dst[1] = v.y; dst[2] = v.z; dst[3] = v.w;
    }
    __syncthreads();

    const int vlen = valid_lens[b];

    {
        const int q = tid >> 4, sg = tid & 15;
        float a0 = 0.f, a1 = 0.f, a2 = 0.f, a3 = 0.f;
        const float* qrow = &qs[q * 64];
#pragma unroll
        for (int d = 0; d < 64; d++) {
            float qv = qrow[d];
            float4 kf = *(const float4*)&ks_t[d * 68 + sg * 4];
            a0 = fmaf(qv, kf.x, a0);
            a1 = fmaf(qv, kf.y, a1);
            a2 = fmaf(qv, kf.z, a2);
            a3 = fmaf(qv, kf.w, a3);
        }
        const int s0 = sg * 4;
        sc[q * 64 + s0 + 0] = (s0 + 0 < vlen) ? a0 * scale : NEGV;
        sc[q * 64 + s0 + 1] = (s0 + 1 < vlen) ? a1 * scale : NEGV;
        sc[q * 64 + s0 + 2] = (s0 + 2 < vlen) ? a2 * scale : NEGV;
        sc[q * 64 + s0 + 3] = (s0 + 3 < vlen) ? a3 * scale : NEGV;
    }
    __syncthreads();

    for (int rep = 0; rep < 2; rep++) {
        const int q = wid * 2 + rep;
        float v0 = sc[q * 64 + lane], v1 = sc[q * 64 + lane + 32];
        int i0 = lane, i1 = lane + 32;
        float vals[8];
#pragma unroll
        for (int j = 0; j < 8; j++) {
            float m; int mi;
            if (v0 >= v1) { m = v0; mi = i0; } else { m = v1; mi = i1; }
#pragma unroll
            for (int o = 16; o; o >>= 1) {
                float om = __shfl_xor_sync(~0u, m, o);
                int   oi = __shfl_xor_sync(~0u, mi, o);
                if (om > m || (om == m && oi < mi)) { m = om; mi = oi; }
            }
            if (lane == 0) { sidx[q * 8 + j] = mi; vals[j] = m; }
            if (i0 == mi) v0 = -3.0e38f;
            if (i1 == mi) v1 = -3.0e38f;
        }
        if (lane == 0) {
            const float m = vals[0];
            float e[8], sum = 0.f;
#pragma unroll
            for (int j = 0; j < 8; j++) { e[j] = expf(vals[j] - m); sum += e[j]; }
            const float inv = 1.f / sum;
#pragma unroll
            for (int j = 0; j < 8; j++) sw8[q * 8 + j] = e[j] * inv;
        }
    }
    __syncthreads();

    {
        const int t = lane >> 1, hf = lane & 1;
        for (int kk = 0; kk < 16; kk++) {
            const int q = wid * 2 + (kk >> 3);
            const int j = kk & 7;
            const int row = sidx[q * 8 + j] * 16 + t;
            const uint32_t* kr = (const uint32_t*)kv + row * 33 + hf * 16;
            const float* qr = &qt[q * 64 + hf * 32];
            float acc = 0.f;
#pragma unroll
            for (int it = 0; it < 16; it++) {
                float2 kf = __half22float2(*(const __half2*)&kr[it]);
                float2 q2 = *(const float2*)&qr[it * 2];
                acc = fmaf(q2.x, kf.x, acc);
                acc = fmaf(q2.y, kf.y, acc);
            }
            acc += __shfl_xor_sync(~0u, acc, 1);
            if (hf == 0) cw[q * 128 + j * 16 + t] = acc * scale;
        }
    }
    __syncthreads();

#pragma unroll
    for (int k = 0; k < 16; k++) {
        int idx = tid + k * 512;
        int r = idx >> 3, c = idx & 7;
        uint4 v = *(const uint4*)&g_v16h[((size_t)(b * 1024) + r) * 512 + h * 64 + c * 8];
        uint32_t* dst = (uint32_t*)kv + r * 33 + c * 4;
        dst[0] = v.x; dst[1] = v.y; dst[2] = v.z; dst[3] = v.w;
    }
    if (tid < 256) {
        const int q = tid >> 3, j = tid & 7;
        float* c = &cw[q * 128 + j * 16];
        float m = c[0];
#pragma unroll
        for (int t = 1; t < 16; t++) m = fmaxf(m, c[t]);
        float e[16], sum = 0.f;
#pragma unroll
        for (int t = 0; t < 16; t++) { e[t] = expf(c[t] - m); sum += e[t]; }
        const float f = sw8[q * 8 + j] / sum;
#pragma unroll
        for (int t = 0; t < 16; t++) c[t] = e[t] * f;
    }
    __syncthreads();

    {
        const int q = tid >> 4, dg = tid & 15;
        float a0 = 0.f, a1 = 0.f, b0 = 0.f, b1 = 0.f;
#pragma unroll
        for (int j = 0; j < 8; j++) {
            const int rbase = sidx[q * 8 + j] * 16;
            const float* cwr = &cw[q * 128 + j * 16];
#pragma unroll
            for (int t = 0; t < 16; t++) {
                const float w = cwr[t];
                const uint32_t* vr = (const uint32_t*)kv + (rbase + t) * 33;
                float2 va = __half22float2(*(const __half2*)&vr[dg]);
                float2 vb = __half22float2(*(const __half2*)&vr[dg + 16]);
                a0 = fmaf(w, va.x, a0);
                a1 = fmaf(w, va.y, a1);
                b0 = fmaf(w, vb.x, b0);
                b1 = fmaf(w, vb.y, b1);
            }
        }
        const size_t off = (size_t)(qbase + q) * 512 + h * 64;
        *(__half2*)&g_at_h[off + 2 * dg]      = __floats2half2_rn(a0, a1);
        *(__half2*)&g_at_h[off + 32 + 2 * dg] = __floats2half2_rn(b0, b1);
    }
}

// ---------------------------------------------------------------------------
extern "C" void kernel_launch(void* const* d_in, const int* in_sizes, int n_in,
                              void* d_out, int out_size) {
    const float* queries        = (const float*)d_in[0];
    const float* stat_keys      = (const float*)d_in[1];
    const float* token_keys     = (const float*)d_in[2];
    const float* values         = (const float*)d_in[3];
    const int*   stat_valid_len = (const int*)  d_in[4];
    WPtrs ws;
    for (int i = 0; i < 6; i++) ws.p[i] = (const float*)d_in[5 + i];
    float* out = (float*)d_out;

    __half *cq_h, *cq_l, *csk_h, *csk_l, *ctk_h, *cv_h;
    __half *wh, *wl, *at_h, *ktk16, *v16h;
    float *q_stat, *q_tok, *k_stat;
    cudaGetSymbolAddress((void**)&cq_h,  g_cq_h);  cudaGetSymbolAddress((void**)&cq_l,  g_cq_l);
    cudaGetSymbolAddress((void**)&csk_h, g_csk_h); cudaGetSymbolAddress((void**)&csk_l, g_csk_l);
    cudaGetSymbolAddress((void**)&ctk_h, g_ctk_h); cudaGetSymbolAddress((void**)&cv_h,  g_cv_h);
    cudaGetSymbolAddress((void**)&wh,    g_wh);    cudaGetSymbolAddress((void**)&wl,    g_wl);
    cudaGetSymbolAddress((void**)&at_h,  g_at_h);
    cudaGetSymbolAddress((void**)&ktk16, g_ktk16); cudaGetSymbolAddress((void**)&v16h,  g_v16h);
    cudaGetSymbolAddress((void**)&q_stat, g_q_stat);
    cudaGetSymbolAddress((void**)&q_tok,  g_q_tok);
    cudaGetSymbolAddress((void**)&k_stat, g_k_stat);

    const size_t WSZ = (size_t)512 * 512;
    constexpr int SMEM = 2 * (2 * 128 * 80 + 2 * 128 * 80);  // 81920
    constexpr int SMEM_WO = 4 * (64 * 80 + 2 * 64 * 80);     // 61440
    cudaFuncSetAttribute(gemm_batched, cudaFuncAttributeMaxDynamicSharedMemorySize, SMEM);
    cudaFuncSetAttribute(gemm_wo, cudaFuncAttributeMaxDynamicSharedMemorySize, SMEM_WO);
    cudaFuncSetAttribute(attn2, cudaFuncAttributeMaxDynamicSharedMemorySize, ATTN_SMEM);

    // 1) fused prep: weights (1536 blocks) + input conversion (8704 blocks)
    prep_all<<<10240, 256>>>(ws, queries, stat_keys, token_keys, values);

    // 2) all five projections in one launch (560 CTAs)
    GemmBatch gb;
    gb.Ah[0] = cq_h;  gb.Al[0] = cq_l;  gb.Bh[0] = wh;           gb.Bl[0] = wl;
    gb.C0[0] = q_stat; gb.C1[0] = q_tok; gb.Ho[0] = nullptr; gb.nbx[0] = 8; gb.cnt[0] = 32;
    gb.Ah[1] = csk_h; gb.Al[1] = csk_l; gb.Bh[1] = wh + 2 * WSZ; gb.Bl[1] = wl + 2 * WSZ;
    gb.C0[1] = k_stat; gb.C1[1] = nullptr; gb.Ho[1] = nullptr; gb.nbx[1] = 4; gb.cnt[1] = 16;
    gb.Ah[2] = ctk_h; gb.Al[2] = nullptr; gb.Bh[2] = wh + 3 * WSZ; gb.Bl[2] = nullptr;
    gb.C0[2] = nullptr; gb.C1[2] = nullptr; gb.Ho[2] = ktk16; gb.nbx[2] = 4; gb.cnt[2] = 256;
    gb.Ah[3] = cv_h;  gb.Al[3] = nullptr; gb.Bh[3] = wh + 4 * WSZ; gb.Bl[3] = nullptr;
    gb.C0[3] = nullptr; gb.C1[3] = nullptr; gb.Ho[3] = v16h; gb.nbx[3] = 4; gb.cnt[3] = 256;
    gemm_batched<<<560, 256, SMEM>>>(gb);

    // 3) attention v2
    attn2<<<dim3(64, 2), 512, ATTN_SMEM>>>(stat_valid_len);

    // 4) output projection: 64 CTAs, 4-stage pipeline
    gemm_wo<<<dim3(8, 8), 128, SMEM_WO>>>(at_h, wh + 5 * WSZ, wl + 5 * WSZ, out);
}

// round 15
// speedup vs baseline: 1.6371x; 1.1845x over previous
#include <cuda_runtime.h>
#include <cuda_fp16.h>
#include <cstdint>
#include <math.h>

#define B_   8
#define Q_   64
#define S_   64
#define T_   64
#define H_   8
#define DH_  64
#define NH_  512
#define NEGV (-1e6f)

// ---------------------------------------------------------------------------
// Scratch (device globals)
// ---------------------------------------------------------------------------
__device__ __half g_cq_h [512 * 512],  g_cq_l [512 * 512];    // queries hi/lo
__device__ __half g_csk_h[512 * 512],  g_csk_l[512 * 512];    // stat_keys hi/lo
__device__ __half g_ctk_h[8192 * 512];                        // gathered token_keys fp16
__device__ __half g_cv_h [8192 * 512];                        // gathered values fp16
__device__ __half g_wh[6 * 512 * 512], g_wl[6 * 512 * 512];   // W^T [N,K] fp16 hi/lo
__device__ float g_q_stat[512 * 512];
__device__ float g_q_tok [512 * 512];
__device__ float g_k_stat[512 * 512];
__device__ __half g_ktk16[8192 * 512];                        // projected token keys (fp16)
__device__ __half g_v16h [8192 * 512];                        // projected values (fp16)
__device__ __half g_at_h[512 * 512];                          // attn out fp16

// ---------------------------------------------------------------------------
// helpers
// ---------------------------------------------------------------------------
__device__ __forceinline__ uint32_t smem_u32(const void* p) {
    uint32_t a;
    asm("{ .reg .u64 t; cvta.to.shared.u64 t, %1; cvt.u32.u64 %0, t; }" : "=r"(a) : "l"(p));
    return a;
}
__device__ __forceinline__ void ldsm_x4(uint32_t* r, uint32_t addr) {
    asm volatile("ldmatrix.sync.aligned.m8n8.x4.shared.b16 {%0,%1,%2,%3}, [%4];"
        : "=r"(r[0]), "=r"(r[1]), "=r"(r[2]), "=r"(r[3]) : "r"(addr));
}
__device__ __forceinline__ void ldsm_x2(uint32_t* r, uint32_t addr) {
    asm volatile("ldmatrix.sync.aligned.m8n8.x2.shared.b16 {%0,%1}, [%2];"
        : "=r"(r[0]), "=r"(r[1]) : "r"(addr));
}
__device__ __forceinline__ void mma16816(float* d, const uint32_t* a, const uint32_t* b) {
    asm volatile("mma.sync.aligned.m16n8k16.row.col.f32.f16.f16.f32 "
        "{%0,%1,%2,%3}, {%4,%5,%6,%7}, {%8,%9}, {%0,%1,%2,%3};"
        : "+f"(d[0]), "+f"(d[1]), "+f"(d[2]), "+f"(d[3])
        : "r"(a[0]), "r"(a[1]), "r"(a[2]), "r"(a[3]), "r"(b[0]), "r"(b[1]));
}
__device__ __forceinline__ void cp16(uint32_t dst, const void* src) {
    asm volatile("cp.async.cg.shared.global [%0], [%1], 16;" :: "r"(dst), "l"(src));
}
#define CP_COMMIT() asm volatile("cp.async.commit_group;" ::: "memory")
#define CP_WAIT2()  asm volatile("cp.async.wait_group 2;" ::: "memory")
#define CP_WAIT1()  asm volatile("cp.async.wait_group 1;" ::: "memory")
#define CP_WAIT0()  asm volatile("cp.async.wait_group 0;" ::: "memory")

__device__ __forceinline__ uint32_t pack2h(float a, float b) {
    return (uint32_t)__half_as_ushort(__float2half(a)) |
           ((uint32_t)__half_as_ushort(__float2half(b)) << 16);
}

// ---------------------------------------------------------------------------
// Fused prep: weight transpose+split (blocks [0,1536)) and input conversion
// (blocks [1536,10240)) in ONE launch.
// ---------------------------------------------------------------------------
struct WPtrs { const float* p[6]; };

__global__ __launch_bounds__(256)
void prep_all(WPtrs ws, const float* __restrict__ q, const float* __restrict__ sk,
              const float* __restrict__ tk, const float* __restrict__ v) {
    __shared__ float t[32][33];
    const int bid = blockIdx.x;
    const int tid = threadIdx.x;

    if (bid < 1536) {
        const int widx = bid / 256;
        const int rem = bid % 256;
        const int n0 = (rem & 15) * 32, k0 = (rem >> 4) * 32;
        const float* W = ws.p[widx];
        __half* hiw = g_wh + (size_t)widx * 512 * 512;
        __half* low = g_wl + (size_t)widx * 512 * 512;
        const int tx = tid & 31, ty = tid >> 5;
#pragma unroll
        for (int i = ty; i < 32; i += 8)
            t[i][tx] = W[(size_t)(k0 + i) * 512 + n0 + tx];
        __syncthreads();
#pragma unroll
        for (int i = ty; i < 32; i += 8) {
            float val = t[tx][i];
            __half h = __float2half(val);
            hiw[(size_t)(n0 + i) * 512 + k0 + tx] = h;
            low[(size_t)(n0 + i) * 512 + k0 + tx] = __float2half(val - __half2float(h));
        }
        return;
    }

    const int cid = bid - 1536;
    int z, base;
    if (cid < 256)       { z = 0; base = cid; }
    else if (cid < 512)  { z = 1; base = cid - 256; }
    else if (cid < 4608) { z = 2; base = cid - 512; }
    else                 { z = 3; base = cid - 4608; }
    const int idx = base * 256 + tid;
    const int r = idx >> 7, c4 = idx & 127;

    if (z < 2) {
        const float* src = z ? sk : q;
        __half* dh = z ? g_csk_h : g_cq_h;
        __half* dl = z ? g_csk_l : g_cq_l;
        float4 x = *(const float4*)&src[(size_t)r * 512 + c4 * 4];
        __half h0 = __float2half(x.x), h1 = __float2half(x.y),
               h2 = __float2half(x.z), h3 = __float2half(x.w);
        uint2 hh, ll;
        hh.x = (uint32_t)__half_as_ushort(h0) | ((uint32_t)__half_as_ushort(h1) << 16);
        hh.y = (uint32_t)__half_as_ushort(h2) | ((uint32_t)__half_as_ushort(h3) << 16);
        ll.x = pack2h(x.x - __half2float(h0), x.y - __half2float(h1));
        ll.y = pack2h(x.z - __half2float(h2), x.w - __half2float(h3));
        *(uint2*)&dh[(size_t)r * 512 + c4 * 4] = hh;
        *(uint2*)&dl[(size_t)r * 512 + c4 * 4] = ll;
    } else {
        const int sr = (r >> 4) * 64 + 48 + (r & 15);
        const float* src = (z == 2) ? tk : v;
        __half* dh = (z == 2) ? g_ctk_h : g_cv_h;
        float4 x = *(const float4*)&src[(size_t)sr * 512 + c4 * 4];
        uint2 hh;
        hh.x = pack2h(x.x, x.y);
        hh.y = pack2h(x.z, x.w);
        *(uint2*)&dh[(size_t)r * 512 + c4 * 4] = hh;
    }
}

// ---------------------------------------------------------------------------
// Batched fp16 GEMM (128x128 tiles).
//   3-term/2-term segments (Al/Bl set): 2-stage pipeline.
//   1-term segments (Al==Bl==nullptr): 4-stage pipeline, single sync/chunk.
// ---------------------------------------------------------------------------
struct GemmBatch {
    const __half *Ah[4], *Al[4], *Bh[4], *Bl[4];
    float *C0[4], *C1[4];
    __half *Ho[4];
    int nbx[4];
    int cnt[4];
};

__global__ __launch_bounds__(256)
void gemm_batched(GemmBatch args) {
    constexpr int MT = 4;
    constexpr uint32_t ABYTES = 128 * 80;              // 10240
    constexpr uint32_t BBYTES = 128 * 80;
    constexpr uint32_t STG    = 2 * ABYTES + 2 * BBYTES;   // 40960 (2-stage path)
    constexpr uint32_t STG1   = ABYTES + BBYTES;           // 20480 (4-stage path)
    extern __shared__ char smem[];
    const uint32_t sb = smem_u32(smem);

    int id = blockIdx.x, s = 0;
#pragma unroll
    for (int i = 0; i < 3; i++) {
        bool adv = (id >= args.cnt[s]);
        if (adv) { id -= args.cnt[s]; s++; }
    }
    const __half* Ah = args.Ah[s];
    const __half* Al = args.Al[s];
    const __half* Bh = args.Bh[s];
    const __half* Bl = args.Bl[s];
    float* C0 = args.C0[s];
    float* C1 = args.C1[s];
    __half* Ho = args.Ho[s];
    const int nbx = args.nbx[s];
    const int bx = id % nbx, by = id / nbx;
    const int m0 = by * 128, n0 = bx * 128;

    const int tid = threadIdx.x;
    const int wid = tid >> 5, lane = tid & 31;
    const int wm = wid >> 2, wn = wid & 3;

    const uint32_t rowA = (uint32_t)(wm * 64 + (lane & 7) + ((lane >> 3) & 1) * 8);
    const uint32_t colA = (uint32_t)(((lane >> 4) & 1) * 16);
    const uint32_t oA = rowA * 80 + colA;
    const uint32_t rowB = (uint32_t)(wn * 32 + (lane & 7));
    const uint32_t colB = (uint32_t)(((lane >> 3) & 1) * 16);
    const uint32_t oB = rowB * 80 + colB;

    float acc[MT][4][4];
#pragma unroll
    for (int i = 0; i < MT; i++)
#pragma unroll
        for (int j = 0; j < 4; j++)
#pragma unroll
            for (int e = 0; e < 4; e++) acc[i][j][e] = 0.f;

    if (!Al && !Bl) {
        // ================= 1-term fast path: 4-stage, 1 sync/chunk =========
        auto load1 = [&](int st, int kc) {
            const int k0 = kc * 32;
            const uint32_t base = sb + st * STG1;
#pragma unroll
            for (int i = 0; i < 2; i++) {
                int c = tid + i * 256;
                int r = c >> 2, qq = c & 3;
                cp16(base + r * 80 + qq * 16,
                     Ah + (size_t)(m0 + r) * 512 + k0 + qq * 8);
                cp16(base + ABYTES + r * 80 + qq * 16,
                     Bh + (size_t)(n0 + r) * 512 + k0 + qq * 8);
            }
        };
        load1(0, 0); CP_COMMIT();
        load1(1, 1); CP_COMMIT();
        load1(2, 2); CP_COMMIT();

        for (int kc = 0; kc < 16; kc++) {
            if (kc <= 13) { CP_WAIT2(); }
            else if (kc == 14) { CP_WAIT1(); }
            else { CP_WAIT0(); }
            __syncthreads();
            const uint32_t so = sb + (kc & 3) * STG1;
#pragma unroll
            for (int ks = 0; ks < 2; ks++) {
                uint32_t bh[4][2];
#pragma unroll
                for (int ni = 0; ni < 4; ni++)
                    ldsm_x2(bh[ni], so + ABYTES + oB + ni * 640 + ks * 32);
#pragma unroll
                for (int mi = 0; mi < MT; mi++) {
                    uint32_t ah[4];
                    ldsm_x4(ah, so + oA + mi * 1280 + ks * 32);
#pragma unroll
                    for (int ni = 0; ni < 4; ni++) mma16816(acc[mi][ni], ah, bh[ni]);
                }
            }
            if (kc + 3 < 16) { load1((kc + 3) & 3, kc + 3); CP_COMMIT(); }
        }
    } else {
        // ================= multi-term path: 2-stage =========================
        const uint32_t oAh = oA;
        const uint32_t oAl = oA + ABYTES;
        const uint32_t oBh = 2 * ABYTES + oB;
        const uint32_t oBl = oBh + BBYTES;

        auto load_stage = [&](int st, int kc) {
            const int k0 = kc * 32;
            const uint32_t base = sb + st * STG;
#pragma unroll
            for (int i = 0; i < 2; i++) {
                int c = tid + i * 256;
                int r = c >> 2, qq = c & 3;
                uint32_t dst = base + r * 80 + qq * 16;
                const size_t ga = (size_t)(m0 + r) * 512 + k0 + qq * 8;
                cp16(dst, Ah + ga);
                if (Al) cp16(dst + ABYTES, Al + ga);
                uint32_t dstB = base + 2 * ABYTES + r * 80 + qq * 16;
                const size_t gb = (size_t)(n0 + r) * 512 + k0 + qq * 8;
                cp16(dstB, Bh + gb);
                if (Bl) cp16(dstB + BBYTES, Bl + gb);
            }
        };

        load_stage(0, 0); CP_COMMIT();
        load_stage(1, 1); CP_COMMIT();

        for (int kc = 0; kc < 16; kc++) {
            if (kc < 15) { CP_WAIT1(); } else { CP_WAIT0(); }
            __syncthreads();
            const uint32_t so = sb + (kc & 1) * STG;
#pragma unroll
            for (int ks = 0; ks < 2; ks++) {
                uint32_t bh[4][2], bl[4][2];
#pragma unroll
                for (int ni = 0; ni < 4; ni++) ldsm_x2(bh[ni], so + oBh + ni * 640 + ks * 32);
                if (Bl) {
#pragma unroll
                    for (int ni = 0; ni < 4; ni++) ldsm_x2(bl[ni], so + oBl + ni * 640 + ks * 32);
                }
#pragma unroll
                for (int mi = 0; mi < MT; mi++) {
                    uint32_t ah[4];
                    ldsm_x4(ah, so + oAh + mi * 1280 + ks * 32);
#pragma unroll
                    for (int ni = 0; ni < 4; ni++) mma16816(acc[mi][ni], ah, bh[ni]);
                    if (Bl) {
#pragma unroll
                        for (int ni = 0; ni < 4; ni++) mma16816(acc[mi][ni], ah, bl[ni]);
                    }
                    if (Al) {
                        uint32_t al[4];
                        ldsm_x4(al, so + oAl + mi * 1280 + ks * 32);
#pragma unroll
                        for (int ni = 0; ni < 4; ni++) mma16816(acc[mi][ni], al, bh[ni]);
                    }
                }
            }
            __syncthreads();
            if (kc + 2 < 16) { load_stage(kc & 1, kc + 2); }
            CP_COMMIT();
        }
    }

    const int mrow = m0 + wm * 64 + (lane >> 2);
    const int ncol = n0 + wn * 32 + (lane & 3) * 2;
#pragma unroll
    for (int mi = 0; mi < MT; mi++) {
#pragma unroll
        for (int ni = 0; ni < 4; ni++) {
            int col = ncol + ni * 8;
            int r0 = mrow + mi * 16;
            if (Ho) {
                *(__half2*)&Ho[(size_t)r0 * 512 + col] =
                    __floats2half2_rn(acc[mi][ni][0], acc[mi][ni][1]);
                *(__half2*)&Ho[(size_t)(r0 + 8) * 512 + col] =
                    __floats2half2_rn(acc[mi][ni][2], acc[mi][ni][3]);
            } else {
                float* dst = (C1 && col >= 512) ? (C1 + col - 512) : (C0 + col);
                *(float2*)&dst[(size_t)r0 * 512]       = make_float2(acc[mi][ni][0], acc[mi][ni][1]);
                *(float2*)&dst[(size_t)(r0 + 8) * 512] = make_float2(acc[mi][ni][2], acc[mi][ni][3]);
            }
        }
    }
}

// ---------------------------------------------------------------------------
// Small GEMM for Wo: 64x64 tiles, 4-stage pipeline (round 14, passing).
// ---------------------------------------------------------------------------
__global__ __launch_bounds__(128)
void gemm_wo(const __half* __restrict__ Ah, const __half* __restrict__ Bh,
             const __half* __restrict__ Bl, float* __restrict__ C) {
    constexpr uint32_t ABYTES = 64 * 80;
    constexpr uint32_t BBYTES = 64 * 80;
    constexpr uint32_t STG    = ABYTES + 2 * BBYTES;
    extern __shared__ char smem[];
    const uint32_t sb = smem_u32(smem);

    const int tid = threadIdx.x;
    const int wid = tid >> 5, lane = tid & 31;
    const int wm = wid >> 1, wn = wid & 1;
    const int m0 = blockIdx.y * 64, n0 = blockIdx.x * 64;

    const uint32_t rowA = (uint32_t)(wm * 32 + (lane & 7) + ((lane >> 3) & 1) * 8);
    const uint32_t colA = (uint32_t)(((lane >> 4) & 1) * 16);
    const uint32_t oAh = rowA * 80 + colA;
    const uint32_t rowB = (uint32_t)(wn * 32 + (lane & 7));
    const uint32_t colB = (uint32_t)(((lane >> 3) & 1) * 16);
    const uint32_t oBh = ABYTES + rowB * 80 + colB;
    const uint32_t oBl = oBh + BBYTES;

    float acc[2][4][4];
#pragma unroll
    for (int i = 0; i < 2; i++)
#pragma unroll
        for (int j = 0; j < 4; j++)
#pragma unroll
            for (int e = 0; e < 4; e++) acc[i][j][e] = 0.f;

    auto load_stage = [&](int st, int kc) {
        const int k0 = kc * 32;
        const uint32_t base = sb + st * STG;
#pragma unroll
        for (int i = 0; i < 2; i++) {
            int c = tid + i * 128;
            int r = c >> 2, qq = c & 3;
            cp16(base + r * 80 + qq * 16, Ah + (size_t)(m0 + r) * 512 + k0 + qq * 8);
            uint32_t dstB = base + ABYTES + r * 80 + qq * 16;
            const size_t gb = (size_t)(n0 + r) * 512 + k0 + qq * 8;
            cp16(dstB, Bh + gb);
            cp16(dstB + BBYTES, Bl + gb);
        }
    };

    load_stage(0, 0); CP_COMMIT();
    load_stage(1, 1); CP_COMMIT();
    load_stage(2, 2); CP_COMMIT();

    for (int kc = 0; kc < 16; kc++) {
        if (kc <= 13) { CP_WAIT2(); }
        else if (kc == 14) { CP_WAIT1(); }
        else { CP_WAIT0(); }
        __syncthreads();
        const uint32_t so = sb + (kc & 3) * STG;
#pragma unroll
        for (int ks = 0; ks < 2; ks++) {
            uint32_t bh[4][2], bl[4][2];
#pragma unroll
            for (int ni = 0; ni < 4; ni++) ldsm_x2(bh[ni], so + oBh + ni * 640 + ks * 32);
#pragma unroll
            for (int ni = 0; ni < 4; ni++) ldsm_x2(bl[ni], so + oBl + ni * 640 + ks * 32);
#pragma unroll
            for (int mi = 0; mi < 2; mi++) {
                uint32_t ah[4];
                ldsm_x4(ah, so + oAh + mi * 1280 + ks * 32);
#pragma unroll
                for (int ni = 0; ni < 4; ni++) mma16816(acc[mi][ni], ah, bh[ni]);
#pragma unroll
                for (int ni = 0; ni < 4; ni++) mma16816(acc[mi][ni], ah, bl[ni]);
            }
        }
        if (kc + 3 < 16) { load_stage((kc + 3) & 3, kc + 3); CP_COMMIT(); }
    }

    const int mrow = m0 + wm * 32 + (lane >> 2);
    const int ncol = n0 + wn * 32 + (lane & 3) * 2;
#pragma unroll
    for (int mi = 0; mi < 2; mi++) {
#pragma unroll
        for (int ni = 0; ni < 4; ni++) {
            int col = ncol + ni * 8;
            int r0 = mrow + mi * 16;
            *(float2*)&C[(size_t)r0 * 512 + col]       = make_float2(acc[mi][ni][0], acc[mi][ni][1]);
            *(float2*)&C[(size_t)(r0 + 8) * 512 + col] = make_float2(acc[mi][ni][2], acc[mi][ni][3]);
        }
    }
}

// ---------------------------------------------------------------------------
// Hierarchical attention v2: block per (b,h,q-half). fp16 output (hi only).
// ---------------------------------------------------------------------------
#define ATTN_SMEM 195584

__global__ __launch_bounds__(512)
void attn2(const int* __restrict__ valid_lens) {
    extern __shared__ char sm[];
    __half* kv   = (__half*)sm;
    float*  ks_t = (float*)(sm + 135168);
    float*  qs   = (float*)(sm + 135168 + 17408);
    float*  qt   = qs + 2048;
    float*  sc   = qt + 2048;
    float*  cw   = sc + 2048;
    int*    sidx = (int*)(cw + 4096);
    float*  sw8  = (float*)(sidx + 256);

    const int bh = blockIdx.x;
    const int b = bh >> 3, h = bh & 7;
    const int qh = blockIdx.y;
    const int qbase = b * 64 + qh * 32;
    const int tid = threadIdx.x, wid = tid >> 5, lane = tid & 31;
    const float scale = 0.125f;

#pragma unroll
    for (int k = 0; k < 2; k++) {
        int i4 = tid + k * 512;
        int s = i4 >> 4, dq = i4 & 15;
        float4 v = *(const float4*)&g_k_stat[(size_t)(b * 64 + s) * 512 + h * 64 + dq * 4];
        ks_t[(dq * 4 + 0) * 68 + s] = v.x;
        ks_t[(dq * 4 + 1) * 68 + s] = v.y;
        ks_t[(dq * 4 + 2) * 68 + s] = v.z;
        ks_t[(dq * 4 + 3) * 68 + s] = v.w;
    }
    {
        int q = tid >> 4, dq = tid & 15;
        *(float4*)&qs[q * 64 + dq * 4] =
            *(const float4*)&g_q_stat[(size_t)(qbase + q) * 512 + h * 64 + dq * 4];
        *(float4*)&qt[q * 64 + dq * 4] =
            *(const float4*)&g_q_tok[(size_t)(qbase + q) * 512 + h * 64 + dq * 4];
    }
#pragma unroll
    for (int k = 0; k < 16; k++) {
        int idx = tid + k * 512;
        int r = idx >> 3, c = idx & 7;
        uint4 v = *(const uint4*)&g_ktk16[((size_t)(b * 1024) + r) * 512 + h * 64 + c * 8];
        uint32_t* dst = (uint32_t*)kv + r * 33 + c * 4;
        dst[0] = v.x; dst[1] = v.y; dst[2] = v.z; dst[3] = v.w;
    }
    __syncthreads();

    const int vlen = valid_lens[b];

    {
        const int q = tid >> 4, sg = tid & 15;
        float a0 = 0.f, a1 = 0.f, a2 = 0.f, a3 = 0.f;
        const float* qrow = &qs[q * 64];
#pragma unroll
        for (int d = 0; d < 64; d++) {
            float qv = qrow[d];
            float4 kf = *(const float4*)&ks_t[d * 68 + sg * 4];
            a0 = fmaf(qv, kf.x, a0);
            a1 = fmaf(qv, kf.y, a1);
            a2 = fmaf(qv, kf.z, a2);
            a3 = fmaf(qv, kf.w, a3);
        }
        const int s0 = sg * 4;
        sc[q * 64 + s0 + 0] = (s0 + 0 < vlen) ? a0 * scale : NEGV;
        sc[q * 64 + s0 + 1] = (s0 + 1 < vlen) ? a1 * scale : NEGV;
        sc[q * 64 + s0 + 2] = (s0 + 2 < vlen) ? a2 * scale : NEGV;
        sc[q * 64 + s0 + 3] = (s0 + 3 < vlen) ? a3 * scale : NEGV;
    }
    __syncthreads();

    for (int rep = 0; rep < 2; rep++) {
        const int q = wid * 2 + rep;
        float v0 = sc[q * 64 + lane], v1 = sc[q * 64 + lane + 32];
        int i0 = lane, i1 = lane + 32;
        float vals[8];
#pragma unroll
        for (int j = 0; j < 8; j++) {
            float m; int mi;
            if (v0 >= v1) { m = v0; mi = i0; } else { m = v1; mi = i1; }
#pragma unroll
            for (int o = 16; o; o >>= 1) {
                float om = __shfl_xor_sync(~0u, m, o);
                int   oi = __shfl_xor_sync(~0u, mi, o);
                if (om > m || (om == m && oi < mi)) { m = om; mi = oi; }
            }
            if (lane == 0) { sidx[q * 8 + j] = mi; vals[j] = m; }
            if (i0 == mi) v0 = -3.0e38f;
            if (i1 == mi) v1 = -3.0e38f;
        }
        if (lane == 0) {
            const float m = vals[0];
            float e[8], sum = 0.f;
#pragma unroll
            for (int j = 0; j < 8; j++) { e[j] = expf(vals[j] - m); sum += e[j]; }
            const float inv = 1.f / sum;
#pragma unroll
            for (int j = 0; j < 8; j++) sw8[q * 8 + j] = e[j] * inv;
        }
    }
    __syncthreads();

    {
        const int t = lane >> 1, hf = lane & 1;
        for (int kk = 0; kk < 16; kk++) {
            const int q = wid * 2 + (kk >> 3);
            const int j = kk & 7;
            const int row = sidx[q * 8 + j] * 16 + t;
            const uint32_t* kr = (const uint32_t*)kv + row * 33 + hf * 16;
            const float* qr = &qt[q * 64 + hf * 32];
            float acc = 0.f;
#pragma unroll
            for (int it = 0; it < 16; it++) {
                float2 kf = __half22float2(*(const __half2*)&kr[it]);
                float2 q2 = *(const float2*)&qr[it * 2];
                acc = fmaf(q2.x, kf.x, acc);
                acc = fmaf(q2.y, kf.y, acc);
            }
            acc += __shfl_xor_sync(~0u, acc, 1);
            if (hf == 0) cw[q * 128 + j * 16 + t] = acc * scale;
        }
    }
    __syncthreads();

#pragma unroll
    for (int k = 0; k < 16; k++) {
        int idx = tid + k * 512;
        int r = idx >> 3, c = idx & 7;
        uint4 v = *(const uint4*)&g_v16h[((size_t)(b * 1024) + r) * 512 + h * 64 + c * 8];
        uint32_t* dst = (uint32_t*)kv + r * 33 + c * 4;
        dst[0] = v.x; dst[1] = v.y; dst[2] = v.z; dst[3] = v.w;
    }
    if (tid < 256) {
        const int q = tid >> 3, j = tid & 7;
        float* c = &cw[q * 128 + j * 16];
        float m = c[0];
#pragma unroll
        for (int t = 1; t < 16; t++) m = fmaxf(m, c[t]);
        float e[16], sum = 0.f;
#pragma unroll
        for (int t = 0; t < 16; t++) { e[t] = expf(c[t] - m); sum += e[t]; }
        const float f = sw8[q * 8 + j] / sum;
#pragma unroll
        for (int t = 0; t < 16; t++) c[t] = e[t] * f;
    }
    __syncthreads();

    {
        const int q = tid >> 4, dg = tid & 15;
        float a0 = 0.f, a1 = 0.f, b0 = 0.f, b1 = 0.f;
#pragma unroll
        for (int j = 0; j < 8; j++) {
            const int rbase = sidx[q * 8 + j] * 16;
            const float* cwr = &cw[q * 128 + j * 16];
#pragma unroll
            for (int t = 0; t < 16; t++) {
                const float w = cwr[t];
                const uint32_t* vr = (const uint32_t*)kv + (rbase + t) * 33;
                float2 va = __half22float2(*(const __half2*)&vr[dg]);
                float2 vb = __half22float2(*(const __half2*)&vr[dg + 16]);
                a0 = fmaf(w, va.x, a0);
                a1 = fmaf(w, va.y, a1);
                b0 = fmaf(w, vb.x, b0);
                b1 = fmaf(w, vb.y, b1);
            }
        }
        const size_t off = (size_t)(qbase + q) * 512 + h * 64;
        *(__half2*)&g_at_h[off + 2 * dg]      = __floats2half2_rn(a0, a1);
        *(__half2*)&g_at_h[off + 32 + 2 * dg] = __floats2half2_rn(b0, b1);
    }
}

// ---------------------------------------------------------------------------
extern "C" void kernel_launch(void* const* d_in, const int* in_sizes, int n_in,
                              void* d_out, int out_size) {
    const float* queries        = (const float*)d_in[0];
    const float* stat_keys      = (const float*)d_in[1];
    const float* token_keys     = (const float*)d_in[2];
    const float* values         = (const float*)d_in[3];
    const int*   stat_valid_len = (const int*)  d_in[4];
    WPtrs ws;
    for (int i = 0; i < 6; i++) ws.p[i] = (const float*)d_in[5 + i];
    float* out = (float*)d_out;

    __half *cq_h, *cq_l, *csk_h, *csk_l, *ctk_h, *cv_h;
    __half *wh, *wl, *at_h, *ktk16, *v16h;
    float *q_stat, *q_tok, *k_stat;
    cudaGetSymbolAddress((void**)&cq_h,  g_cq_h);  cudaGetSymbolAddress((void**)&cq_l,  g_cq_l);
    cudaGetSymbolAddress((void**)&csk_h, g_csk_h); cudaGetSymbolAddress((void**)&csk_l, g_csk_l);
    cudaGetSymbolAddress((void**)&ctk_h, g_ctk_h); cudaGetSymbolAddress((void**)&cv_h,  g_cv_h);
    cudaGetSymbolAddress((void**)&wh,    g_wh);    cudaGetSymbolAddress((void**)&wl,    g_wl);
    cudaGetSymbolAddress((void**)&at_h,  g_at_h);
    cudaGetSymbolAddress((void**)&ktk16, g_ktk16); cudaGetSymbolAddress((void**)&v16h,  g_v16h);
    cudaGetSymbolAddress((void**)&q_stat, g_q_stat);
    cudaGetSymbolAddress((void**)&q_tok,  g_q_tok);
    cudaGetSymbolAddress((void**)&k_stat, g_k_stat);

    const size_t WSZ = (size_t)512 * 512;
    constexpr int SMEM = 2 * (2 * 128 * 80 + 2 * 128 * 80);  // 81920
    constexpr int SMEM_WO = 4 * (64 * 80 + 2 * 64 * 80);     // 61440
    cudaFuncSetAttribute(gemm_batched, cudaFuncAttributeMaxDynamicSharedMemorySize, SMEM);
    cudaFuncSetAttribute(gemm_wo, cudaFuncAttributeMaxDynamicSharedMemorySize, SMEM_WO);
    cudaFuncSetAttribute(attn2, cudaFuncAttributeMaxDynamicSharedMemorySize, ATTN_SMEM);

    // 1) fused prep
    prep_all<<<10240, 256>>>(ws, queries, stat_keys, token_keys, values);

    // 2) all five projections in one launch (560 CTAs)
    GemmBatch gb;
    gb.Ah[0] = cq_h;  gb.Al[0] = cq_l;  gb.Bh[0] = wh;           gb.Bl[0] = wl;
    gb.C0[0] = q_stat; gb.C1[0] = q_tok; gb.Ho[0] = nullptr; gb.nbx[0] = 8; gb.cnt[0] = 32;
    gb.Ah[1] = csk_h; gb.Al[1] = csk_l; gb.Bh[1] = wh + 2 * WSZ; gb.Bl[1] = wl + 2 * WSZ;
    gb.C0[1] = k_stat; gb.C1[1] = nullptr; gb.Ho[1] = nullptr; gb.nbx[1] = 4; gb.cnt[1] = 16;
    gb.Ah[2] = ctk_h; gb.Al[2] = nullptr; gb.Bh[2] = wh + 3 * WSZ; gb.Bl[2] = nullptr;
    gb.C0[2] = nullptr; gb.C1[2] = nullptr; gb.Ho[2] = ktk16; gb.nbx[2] = 4; gb.cnt[2] = 256;
    gb.Ah[3] = cv_h;  gb.Al[3] = nullptr; gb.Bh[3] = wh + 4 * WSZ; gb.Bl[3] = nullptr;
    gb.C0[3] = nullptr; gb.C1[3] = nullptr; gb.Ho[3] = v16h; gb.nbx[3] = 4; gb.cnt[3] = 256;
    gemm_batched<<<560, 256, SMEM>>>(gb);

    // 3) attention v2
    attn2<<<dim3(64, 2), 512, ATTN_SMEM>>>(stat_valid_len);

    // 4) output projection
    gemm_wo<<<dim3(8, 8), 128, SMEM_WO>>>(at_h, wh + 5 * WSZ, wl + 5 * WSZ, out);
}

// round 16
// speedup vs baseline: 1.6403x; 1.0019x over previous
#include <cuda_runtime.h>
#include <cuda_fp16.h>
#include <cstdint>
#include <math.h>

#define B_   8
#define Q_   64
#define S_   64
#define T_   64
#define H_   8
#define DH_  64
#define NH_  512
#define NEGV (-1e6f)

// ---------------------------------------------------------------------------
// Scratch (device globals)
// ---------------------------------------------------------------------------
__device__ __half g_cq_h [512 * 512],  g_cq_l [512 * 512];    // queries hi/lo
__device__ __half g_csk_h[512 * 512],  g_csk_l[512 * 512];    // stat_keys hi/lo
__device__ __half g_ctk_h[8192 * 512];                        // gathered token_keys fp16
__device__ __half g_cv_h [8192 * 512];                        // gathered values fp16
__device__ __half g_wh[6 * 512 * 512], g_wl[6 * 512 * 512];   // W^T [N,K] fp16 hi/lo
__device__ float g_q_stat[512 * 512];
__device__ float g_q_tok [512 * 512];
__device__ float g_k_stat[512 * 512];
__device__ __half g_ktk16[8192 * 512];                        // projected token keys (fp16)
__device__ __half g_v16h [8192 * 512];                        // projected values (fp16)
__device__ __half g_at_h[512 * 512];                          // attn out fp16

// ---------------------------------------------------------------------------
// helpers
// ---------------------------------------------------------------------------
__device__ __forceinline__ uint32_t smem_u32(const void* p) {
    uint32_t a;
    asm("{ .reg .u64 t; cvta.to.shared.u64 t, %1; cvt.u32.u64 %0, t; }" : "=r"(a) : "l"(p));
    return a;
}
__device__ __forceinline__ void ldsm_x4(uint32_t* r, uint32_t addr) {
    asm volatile("ldmatrix.sync.aligned.m8n8.x4.shared.b16 {%0,%1,%2,%3}, [%4];"
        : "=r"(r[0]), "=r"(r[1]), "=r"(r[2]), "=r"(r[3]) : "r"(addr));
}
__device__ __forceinline__ void ldsm_x2(uint32_t* r, uint32_t addr) {
    asm volatile("ldmatrix.sync.aligned.m8n8.x2.shared.b16 {%0,%1}, [%2];"
        : "=r"(r[0]), "=r"(r[1]) : "r"(addr));
}
__device__ __forceinline__ void mma16816(float* d, const uint32_t* a, const uint32_t* b) {
    asm volatile("mma.sync.aligned.m16n8k16.row.col.f32.f16.f16.f32 "
        "{%0,%1,%2,%3}, {%4,%5,%6,%7}, {%8,%9}, {%0,%1,%2,%3};"
        : "+f"(d[0]), "+f"(d[1]), "+f"(d[2]), "+f"(d[3])
        : "r"(a[0]), "r"(a[1]), "r"(a[2]), "r"(a[3]), "r"(b[0]), "r"(b[1]));
}
__device__ __forceinline__ void cp16(uint32_t dst, const void* src) {
    asm volatile("cp.async.cg.shared.global [%0], [%1], 16;" :: "r"(dst), "l"(src));
}
#define CP_COMMIT() asm volatile("cp.async.commit_group;" ::: "memory")
#define CP_WAIT2()  asm volatile("cp.async.wait_group 2;" ::: "memory")
#define CP_WAIT1()  asm volatile("cp.async.wait_group 1;" ::: "memory")
#define CP_WAIT0()  asm volatile("cp.async.wait_group 0;" ::: "memory")

__device__ __forceinline__ uint32_t pack2h(float a, float b) {
    return (uint32_t)__half_as_ushort(__float2half(a)) |
           ((uint32_t)__half_as_ushort(__float2half(b)) << 16);
}

// ---------------------------------------------------------------------------
// Fused prep: weight transpose+split (blocks [0,1536)) and input conversion
// (blocks [1536,10240)) in ONE launch.
// ---------------------------------------------------------------------------
struct WPtrs { const float* p[6]; };

__global__ __launch_bounds__(256)
void prep_all(WPtrs ws, const float* __restrict__ q, const float* __restrict__ sk,
              const float* __restrict__ tk, const float* __restrict__ v) {
    __shared__ float t[32][33];
    const int bid = blockIdx.x;
    const int tid = threadIdx.x;

    if (bid < 1536) {
        const int widx = bid / 256;
        const int rem = bid % 256;
        const int n0 = (rem & 15) * 32, k0 = (rem >> 4) * 32;
        const float* W = ws.p[widx];
        __half* hiw = g_wh + (size_t)widx * 512 * 512;
        __half* low = g_wl + (size_t)widx * 512 * 512;
        const int tx = tid & 31, ty = tid >> 5;
#pragma unroll
        for (int i = ty; i < 32; i += 8)
            t[i][tx] = W[(size_t)(k0 + i) * 512 + n0 + tx];
        __syncthreads();
#pragma unroll
        for (int i = ty; i < 32; i += 8) {
            float val = t[tx][i];
            __half h = __float2half(val);
            hiw[(size_t)(n0 + i) * 512 + k0 + tx] = h;
            low[(size_t)(n0 + i) * 512 + k0 + tx] = __float2half(val - __half2float(h));
        }
        return;
    }

    const int cid = bid - 1536;
    int z, base;
    if (cid < 256)       { z = 0; base = cid; }
    else if (cid < 512)  { z = 1; base = cid - 256; }
    else if (cid < 4608) { z = 2; base = cid - 512; }
    else                 { z = 3; base = cid - 4608; }
    const int idx = base * 256 + tid;
    const int r = idx >> 7, c4 = idx & 127;

    if (z < 2) {
        const float* src = z ? sk : q;
        __half* dh = z ? g_csk_h : g_cq_h;
        __half* dl = z ? g_csk_l : g_cq_l;
        float4 x = *(const float4*)&src[(size_t)r * 512 + c4 * 4];
        __half h0 = __float2half(x.x), h1 = __float2half(x.y),
               h2 = __float2half(x.z), h3 = __float2half(x.w);
        uint2 hh, ll;
        hh.x = (uint32_t)__half_as_ushort(h0) | ((uint32_t)__half_as_ushort(h1) << 16);
        hh.y = (uint32_t)__half_as_ushort(h2) | ((uint32_t)__half_as_ushort(h3) << 16);
        ll.x = pack2h(x.x - __half2float(h0), x.y - __half2float(h1));
        ll.y = pack2h(x.z - __half2float(h2), x.w - __half2float(h3));
        *(uint2*)&dh[(size_t)r * 512 + c4 * 4] = hh;
        *(uint2*)&dl[(size_t)r * 512 + c4 * 4] = ll;
    } else {
        const int sr = (r >> 4) * 64 + 48 + (r & 15);
        const float* src = (z == 2) ? tk : v;
        __half* dh = (z == 2) ? g_ctk_h : g_cv_h;
        float4 x = *(const float4*)&src[(size_t)sr * 512 + c4 * 4];
        uint2 hh;
        hh.x = pack2h(x.x, x.y);
        hh.y = pack2h(x.z, x.w);
        *(uint2*)&dh[(size_t)r * 512 + c4 * 4] = hh;
    }
}

// ---------------------------------------------------------------------------
// Batched fp16 GEMM (128x128 tiles): multi-term 2-stage / 1-term 4-stage.
// ---------------------------------------------------------------------------
struct GemmBatch {
    const __half *Ah[4], *Al[4], *Bh[4], *Bl[4];
    float *C0[4], *C1[4];
    __half *Ho[4];
    int nbx[4];
    int cnt[4];
};

__global__ __launch_bounds__(256)
void gemm_batched(GemmBatch args) {
    constexpr int MT = 4;
    constexpr uint32_t ABYTES = 128 * 80;
    constexpr uint32_t BBYTES = 128 * 80;
    constexpr uint32_t STG    = 2 * ABYTES + 2 * BBYTES;
    constexpr uint32_t STG1   = ABYTES + BBYTES;
    extern __shared__ char smem[];
    const uint32_t sb = smem_u32(smem);

    int id = blockIdx.x, s = 0;
#pragma unroll
    for (int i = 0; i < 3; i++) {
        bool adv = (id >= args.cnt[s]);
        if (adv) { id -= args.cnt[s]; s++; }
    }
    const __half* Ah = args.Ah[s];
    const __half* Al = args.Al[s];
    const __half* Bh = args.Bh[s];
    const __half* Bl = args.Bl[s];
    float* C0 = args.C0[s];
    float* C1 = args.C1[s];
    __half* Ho = args.Ho[s];
    const int nbx = args.nbx[s];
    const int bx = id % nbx, by = id / nbx;
    const int m0 = by * 128, n0 = bx * 128;

    const int tid = threadIdx.x;
    const int wid = tid >> 5, lane = tid & 31;
    const int wm = wid >> 2, wn = wid & 3;

    const uint32_t rowA = (uint32_t)(wm * 64 + (lane & 7) + ((lane >> 3) & 1) * 8);
    const uint32_t colA = (uint32_t)(((lane >> 4) & 1) * 16);
    const uint32_t oA = rowA * 80 + colA;
    const uint32_t rowB = (uint32_t)(wn * 32 + (lane & 7));
    const uint32_t colB = (uint32_t)(((lane >> 3) & 1) * 16);
    const uint32_t oB = rowB * 80 + colB;

    float acc[MT][4][4];
#pragma unroll
    for (int i = 0; i < MT; i++)
#pragma unroll
        for (int j = 0; j < 4; j++)
#pragma unroll
            for (int e = 0; e < 4; e++) acc[i][j][e] = 0.f;

    if (!Al && !Bl) {
        auto load1 = [&](int st, int kc) {
            const int k0 = kc * 32;
            const uint32_t base = sb + st * STG1;
#pragma unroll
            for (int i = 0; i < 2; i++) {
                int c = tid + i * 256;
                int r = c >> 2, qq = c & 3;
                cp16(base + r * 80 + qq * 16,
                     Ah + (size_t)(m0 + r) * 512 + k0 + qq * 8);
                cp16(base + ABYTES + r * 80 + qq * 16,
                     Bh + (size_t)(n0 + r) * 512 + k0 + qq * 8);
            }
        };
        load1(0, 0); CP_COMMIT();
        load1(1, 1); CP_COMMIT();
        load1(2, 2); CP_COMMIT();

        for (int kc = 0; kc < 16; kc++) {
            if (kc <= 13) { CP_WAIT2(); }
            else if (kc == 14) { CP_WAIT1(); }
            else { CP_WAIT0(); }
            __syncthreads();
            const uint32_t so = sb + (kc & 3) * STG1;
#pragma unroll
            for (int ks = 0; ks < 2; ks++) {
                uint32_t bh[4][2];
#pragma unroll
                for (int ni = 0; ni < 4; ni++)
                    ldsm_x2(bh[ni], so + ABYTES + oB + ni * 640 + ks * 32);
#pragma unroll
                for (int mi = 0; mi < MT; mi++) {
                    uint32_t ah[4];
                    ldsm_x4(ah, so + oA + mi * 1280 + ks * 32);
#pragma unroll
                    for (int ni = 0; ni < 4; ni++) mma16816(acc[mi][ni], ah, bh[ni]);
                }
            }
            if (kc + 3 < 16) { load1((kc + 3) & 3, kc + 3); CP_COMMIT(); }
        }
    } else {
        const uint32_t oAh = oA;
        const uint32_t oAl = oA + ABYTES;
        const uint32_t oBh = 2 * ABYTES + oB;
        const uint32_t oBl = oBh + BBYTES;

        auto load_stage = [&](int st, int kc) {
            const int k0 = kc * 32;
            const uint32_t base = sb + st * STG;
#pragma unroll
            for (int i = 0; i < 2; i++) {
                int c = tid + i * 256;
                int r = c >> 2, qq = c & 3;
                uint32_t dst = base + r * 80 + qq * 16;
                const size_t ga = (size_t)(m0 + r) * 512 + k0 + qq * 8;
                cp16(dst, Ah + ga);
                if (Al) cp16(dst + ABYTES, Al + ga);
                uint32_t dstB = base + 2 * ABYTES + r * 80 + qq * 16;
                const size_t gb = (size_t)(n0 + r) * 512 + k0 + qq * 8;
                cp16(dstB, Bh + gb);
                if (Bl) cp16(dstB + BBYTES, Bl + gb);
            }
        };

        load_stage(0, 0); CP_COMMIT();
        load_stage(1, 1); CP_COMMIT();

        for (int kc = 0; kc < 16; kc++) {
            if (kc < 15) { CP_WAIT1(); } else { CP_WAIT0(); }
            __syncthreads();
            const uint32_t so = sb + (kc & 1) * STG;
#pragma unroll
            for (int ks = 0; ks < 2; ks++) {
                uint32_t bh[4][2], bl[4][2];
#pragma unroll
                for (int ni = 0; ni < 4; ni++) ldsm_x2(bh[ni], so + oBh + ni * 640 + ks * 32);
                if (Bl) {
#pragma unroll
                    for (int ni = 0; ni < 4; ni++) ldsm_x2(bl[ni], so + oBl + ni * 640 + ks * 32);
                }
#pragma unroll
                for (int mi = 0; mi < MT; mi++) {
                    uint32_t ah[4];
                    ldsm_x4(ah, so + oAh + mi * 1280 + ks * 32);
#pragma unroll
                    for (int ni = 0; ni < 4; ni++) mma16816(acc[mi][ni], ah, bh[ni]);
                    if (Bl) {
#pragma unroll
                        for (int ni = 0; ni < 4; ni++) mma16816(acc[mi][ni], ah, bl[ni]);
                    }
                    if (Al) {
                        uint32_t al[4];
                        ldsm_x4(al, so + oAl + mi * 1280 + ks * 32);
#pragma unroll
                        for (int ni = 0; ni < 4; ni++) mma16816(acc[mi][ni], al, bh[ni]);
                    }
                }
            }
            __syncthreads();
            if (kc + 2 < 16) { load_stage(kc & 1, kc + 2); }
            CP_COMMIT();
        }
    }

    const int mrow = m0 + wm * 64 + (lane >> 2);
    const int ncol = n0 + wn * 32 + (lane & 3) * 2;
#pragma unroll
    for (int mi = 0; mi < MT; mi++) {
#pragma unroll
        for (int ni = 0; ni < 4; ni++) {
            int col = ncol + ni * 8;
            int r0 = mrow + mi * 16;
            if (Ho) {
                *(__half2*)&Ho[(size_t)r0 * 512 + col] =
                    __floats2half2_rn(acc[mi][ni][0], acc[mi][ni][1]);
                *(__half2*)&Ho[(size_t)(r0 + 8) * 512 + col] =
                    __floats2half2_rn(acc[mi][ni][2], acc[mi][ni][3]);
            } else {
                float* dst = (C1 && col >= 512) ? (C1 + col - 512) : (C0 + col);
                *(float2*)&dst[(size_t)r0 * 512]       = make_float2(acc[mi][ni][0], acc[mi][ni][1]);
                *(float2*)&dst[(size_t)(r0 + 8) * 512] = make_float2(acc[mi][ni][2], acc[mi][ni][3]);
            }
        }
    }
}

// ---------------------------------------------------------------------------
// Small GEMM for Wo: 32x64 tiles -> 128 CTAs; 128 threads (2x2 warps,
// warp tile 16x32); 4-stage cp.async pipeline. 2-term (B hi/lo).
// ---------------------------------------------------------------------------
__global__ __launch_bounds__(128)
void gemm_wo(const __half* __restrict__ Ah, const __half* __restrict__ Bh,
             const __half* __restrict__ Bl, float* __restrict__ C) {
    constexpr uint32_t ABYTES = 32 * 80;       // 2560
    constexpr uint32_t BBYTES = 64 * 80;       // 5120
    constexpr uint32_t STG    = ABYTES + 2 * BBYTES;   // 12800
    extern __shared__ char smem[];
    const uint32_t sb = smem_u32(smem);

    const int tid = threadIdx.x;
    const int wid = tid >> 5, lane = tid & 31;
    const int wm = wid >> 1, wn = wid & 1;
    const int m0 = blockIdx.y * 32, n0 = blockIdx.x * 64;

    const uint32_t rowA = (uint32_t)(wm * 16 + (lane & 7) + ((lane >> 3) & 1) * 8);
    const uint32_t colA = (uint32_t)(((lane >> 4) & 1) * 16);
    const uint32_t oAh = rowA * 80 + colA;
    const uint32_t rowB = (uint32_t)(wn * 32 + (lane & 7));
    const uint32_t colB = (uint32_t)(((lane >> 3) & 1) * 16);
    const uint32_t oBh = ABYTES + rowB * 80 + colB;
    const uint32_t oBl = oBh + BBYTES;

    float acc[4][4];
#pragma unroll
    for (int j = 0; j < 4; j++)
#pragma unroll
        for (int e = 0; e < 4; e++) acc[j][e] = 0.f;

    auto load_stage = [&](int st, int kc) {
        const int k0 = kc * 32;
        const uint32_t base = sb + st * STG;
        {   // A: 32 rows x 4 chunks = 128
            int r = tid >> 2, qq = tid & 3;
            cp16(base + r * 80 + qq * 16, Ah + (size_t)(m0 + r) * 512 + k0 + qq * 8);
        }
#pragma unroll
        for (int i = 0; i < 2; i++) {   // B hi+lo: 64 rows x 4 chunks each
            int c = tid + i * 128;
            int r = c >> 2, qq = c & 3;
            uint32_t dstB = base + ABYTES + r * 80 + qq * 16;
            const size_t gb = (size_t)(n0 + r) * 512 + k0 + qq * 8;
            cp16(dstB, Bh + gb);
            cp16(dstB + BBYTES, Bl + gb);
        }
    };

    load_stage(0, 0); CP_COMMIT();
    load_stage(1, 1); CP_COMMIT();
    load_stage(2, 2); CP_COMMIT();

    for (int kc = 0; kc < 16; kc++) {
        if (kc <= 13) { CP_WAIT2(); }
        else if (kc == 14) { CP_WAIT1(); }
        else { CP_WAIT0(); }
        __syncthreads();
        const uint32_t so = sb + (kc & 3) * STG;
#pragma unroll
        for (int ks = 0; ks < 2; ks++) {
            uint32_t bh[4][2], bl[4][2];
#pragma unroll
            for (int ni = 0; ni < 4; ni++) ldsm_x2(bh[ni], so + oBh + ni * 640 + ks * 32);
#pragma unroll
            for (int ni = 0; ni < 4; ni++) ldsm_x2(bl[ni], so + oBl + ni * 640 + ks * 32);
            uint32_t ah[4];
            ldsm_x4(ah, so + oAh + ks * 32);
#pragma unroll
            for (int ni = 0; ni < 4; ni++) mma16816(acc[ni], ah, bh[ni]);
#pragma unroll
            for (int ni = 0; ni < 4; ni++) mma16816(acc[ni], ah, bl[ni]);
        }
        if (kc + 3 < 16) { load_stage((kc + 3) & 3, kc + 3); CP_COMMIT(); }
    }

    const int mrow = m0 + wm * 16 + (lane >> 2);
    const int ncol = n0 + wn * 32 + (lane & 3) * 2;
#pragma unroll
    for (int ni = 0; ni < 4; ni++) {
        int col = ncol + ni * 8;
        *(float2*)&C[(size_t)mrow * 512 + col]       = make_float2(acc[ni][0], acc[ni][1]);
        *(float2*)&C[(size_t)(mrow + 8) * 512 + col] = make_float2(acc[ni][2], acc[ni][3]);
    }
}

// ---------------------------------------------------------------------------
// Hierarchical attention v3: block per (b,h,q-half). kv pitch = 36 words
// (144B, 16B-aligned) -> vectorized uint2/float4 smem access in phases C/E.
// ---------------------------------------------------------------------------
#define ATTN_SMEM 207872

__global__ __launch_bounds__(512)
void attn2(const int* __restrict__ valid_lens) {
    extern __shared__ char sm[];
    uint32_t* kvw = (uint32_t*)sm;                              // [1024][36] words
    float*  ks_t = (float*)(sm + 147456);                       // [64][68]
    float*  qs   = (float*)(sm + 164864);                       // [32][64]
    float*  qt   = qs + 2048;
    float*  sc   = qt + 2048;
    float*  cw   = sc + 2048;                                   // [32][128]
    int*    sidx = (int*)(cw + 4096);                           // [32][8]
    float*  sw8  = (float*)(sidx + 256);                        // [32][8]

    const int bh = blockIdx.x;
    const int b = bh >> 3, h = bh & 7;
    const int qh = blockIdx.y;
    const int qbase = b * 64 + qh * 32;
    const int tid = threadIdx.x, wid = tid >> 5, lane = tid & 31;
    const float scale = 0.125f;

#pragma unroll
    for (int k = 0; k < 2; k++) {
        int i4 = tid + k * 512;
        int s = i4 >> 4, dq = i4 & 15;
        float4 v = *(const float4*)&g_k_stat[(size_t)(b * 64 + s) * 512 + h * 64 + dq * 4];
        ks_t[(dq * 4 + 0) * 68 + s] = v.x;
        ks_t[(dq * 4 + 1) * 68 + s] = v.y;
        ks_t[(dq * 4 + 2) * 68 + s] = v.z;
        ks_t[(dq * 4 + 3) * 68 + s] = v.w;
    }
    {
        int q = tid >> 4, dq = tid & 15;
        *(float4*)&qs[q * 64 + dq * 4] =
            *(const float4*)&g_q_stat[(size_t)(qbase + q) * 512 + h * 64 + dq * 4];
        *(float4*)&qt[q * 64 + dq * 4] =
            *(const float4*)&g_q_tok[(size_t)(qbase + q) * 512 + h * 64 + dq * 4];
    }
#pragma unroll
    for (int k = 0; k < 16; k++) {
        int idx = tid + k * 512;
        int r = idx >> 3, c = idx & 7;
        uint4 v = *(const uint4*)&g_ktk16[((size_t)(b * 1024) + r) * 512 + h * 64 + c * 8];
        *(uint4*)(kvw + r * 36 + c * 4) = v;
    }
    __syncthreads();

    const int vlen = valid_lens[b];

    // ---- Phase A: stat scores ----
    {
        const int q = tid >> 4, sg = tid & 15;
        float a0 = 0.f, a1 = 0.f, a2 = 0.f, a3 = 0.f;
        const float* qrow = &qs[q * 64];
#pragma unroll
        for (int d = 0; d < 64; d++) {
            float qv = qrow[d];
            float4 kf = *(const float4*)&ks_t[d * 68 + sg * 4];
            a0 = fmaf(qv, kf.x, a0);
            a1 = fmaf(qv, kf.y, a1);
            a2 = fmaf(qv, kf.z, a2);
            a3 = fmaf(qv, kf.w, a3);
        }
        const int s0 = sg * 4;
        sc[q * 64 + s0 + 0] = (s0 + 0 < vlen) ? a0 * scale : NEGV;
        sc[q * 64 + s0 + 1] = (s0 + 1 < vlen) ? a1 * scale : NEGV;
        sc[q * 64 + s0 + 2] = (s0 + 2 < vlen) ? a2 * scale : NEGV;
        sc[q * 64 + s0 + 3] = (s0 + 3 < vlen) ? a3 * scale : NEGV;
    }
    __syncthreads();

    // ---- Phase B: top-8 per query ----
    for (int rep = 0; rep < 2; rep++) {
        const int q = wid * 2 + rep;
        float v0 = sc[q * 64 + lane], v1 = sc[q * 64 + lane + 32];
        int i0 = lane, i1 = lane + 32;
        float vals[8];
#pragma unroll
        for (int j = 0; j < 8; j++) {
            float m; int mi;
            if (v0 >= v1) { m = v0; mi = i0; } else { m = v1; mi = i1; }
#pragma unroll
            for (int o = 16; o; o >>= 1) {
                float om = __shfl_xor_sync(~0u, m, o);
                int   oi = __shfl_xor_sync(~0u, mi, o);
                if (om > m || (om == m && oi < mi)) { m = om; mi = oi; }
            }
            if (lane == 0) { sidx[q * 8 + j] = mi; vals[j] = m; }
            if (i0 == mi) v0 = -3.0e38f;
            if (i1 == mi) v1 = -3.0e38f;
        }
        if (lane == 0) {
            const float m = vals[0];
            float e[8], sum = 0.f;
#pragma unroll
            for (int j = 0; j < 8; j++) { e[j] = expf(vals[j] - m); sum += e[j]; }
            const float inv = 1.f / sum;
#pragma unroll
            for (int j = 0; j < 8; j++) sw8[q * 8 + j] = e[j] * inv;
        }
    }
    __syncthreads();

    // ---- Phase C: token scores (uint2 K / float4 q loads) ----
    {
        const int t = lane >> 1, hf = lane & 1;
        for (int kk = 0; kk < 16; kk++) {
            const int q = wid * 2 + (kk >> 3);
            const int j = kk & 7;
            const int row = sidx[q * 8 + j] * 16 + t;
            const uint32_t* kr = kvw + row * 36 + hf * 16;
            const float* qr = &qt[q * 64 + hf * 32];
            float acc = 0.f;
#pragma unroll
            for (int it = 0; it < 8; it++) {
                uint2 kk2 = *(const uint2*)&kr[it * 2];
                float2 kf0 = __half22float2(*(const __half2*)&kk2.x);
                float2 kf1 = __half22float2(*(const __half2*)&kk2.y);
                float4 q4 = *(const float4*)&qr[it * 4];
                acc = fmaf(q4.x, kf0.x, acc);
                acc = fmaf(q4.y, kf0.y, acc);
                acc = fmaf(q4.z, kf1.x, acc);
                acc = fmaf(q4.w, kf1.y, acc);
            }
            acc += __shfl_xor_sync(~0u, acc, 1);
            if (hf == 0) cw[q * 128 + j * 16 + t] = acc * scale;
        }
    }
    __syncthreads();

    // ---- stage V tile + Phase D softmax ----
#pragma unroll
    for (int k = 0; k < 16; k++) {
        int idx = tid + k * 512;
        int r = idx >> 3, c = idx & 7;
        uint4 v = *(const uint4*)&g_v16h[((size_t)(b * 1024) + r) * 512 + h * 64 + c * 8];
        *(uint4*)(kvw + r * 36 + c * 4) = v;
    }
    if (tid < 256) {
        const int q = tid >> 3, j = tid & 7;
        float* c = &cw[q * 128 + j * 16];
        float m = c[0];
#pragma unroll
        for (int t = 1; t < 16; t++) m = fmaxf(m, c[t]);
        float e[16], sum = 0.f;
#pragma unroll
        for (int t = 0; t < 16; t++) { e[t] = expf(c[t] - m); sum += e[t]; }
        const float f = sw8[q * 8 + j] / sum;
#pragma unroll
        for (int t = 0; t < 16; t++) c[t] = e[t] * f;
    }
    __syncthreads();

    // ---- Phase E: weighted V reduction (uint2 loads, 4 consecutive d) ----
    {
        const int q = tid >> 4, dg = tid & 15;
        float a0 = 0.f, a1 = 0.f, a2 = 0.f, a3 = 0.f;
#pragma unroll
        for (int j = 0; j < 8; j++) {
            const int rbase = sidx[q * 8 + j] * 16;
            const float* cwr = &cw[q * 128 + j * 16];
#pragma unroll
            for (int t = 0; t < 16; t++) {
                const float w = cwr[t];
                uint2 vv = *(const uint2*)(kvw + (rbase + t) * 36 + 2 * dg);
                float2 va = __half22float2(*(const __half2*)&vv.x);
                float2 vb = __half22float2(*(const __half2*)&vv.y);
                a0 = fmaf(w, va.x, a0);
                a1 = fmaf(w, va.y, a1);
                a2 = fmaf(w, vb.x, a2);
                a3 = fmaf(w, vb.y, a3);
            }
        }
        const size_t off = (size_t)(qbase + q) * 512 + h * 64;
        uint2 o;
        o.x = pack2h(a0, a1);
        o.y = pack2h(a2, a3);
        *(uint2*)&g_at_h[off + 4 * dg] = o;
    }
}

// ---------------------------------------------------------------------------
extern "C" void kernel_launch(void* const* d_in, const int* in_sizes, int n_in,
                              void* d_out, int out_size) {
    const float* queries        = (const float*)d_in[0];
    const float* stat_keys      = (const float*)d_in[1];
    const float* token_keys     = (const float*)d_in[2];
    const float* values         = (const float*)d_in[3];
    const int*   stat_valid_len = (const int*)  d_in[4];
    WPtrs ws;
    for (int i = 0; i < 6; i++) ws.p[i] = (const float*)d_in[5 + i];
    float* out = (float*)d_out;

    __half *cq_h, *cq_l, *csk_h, *csk_l, *ctk_h, *cv_h;
    __half *wh, *wl, *at_h, *ktk16, *v16h;
    float *q_stat, *q_tok, *k_stat;
    cudaGetSymbolAddress((void**)&cq_h,  g_cq_h);  cudaGetSymbolAddress((void**)&cq_l,  g_cq_l);
    cudaGetSymbolAddress((void**)&csk_h, g_csk_h); cudaGetSymbolAddress((void**)&csk_l, g_csk_l);
    cudaGetSymbolAddress((void**)&ctk_h, g_ctk_h); cudaGetSymbolAddress((void**)&cv_h,  g_cv_h);
    cudaGetSymbolAddress((void**)&wh,    g_wh);    cudaGetSymbolAddress((void**)&wl,    g_wl);
    cudaGetSymbolAddress((void**)&at_h,  g_at_h);
    cudaGetSymbolAddress((void**)&ktk16, g_ktk16); cudaGetSymbolAddress((void**)&v16h,  g_v16h);
    cudaGetSymbolAddress((void**)&q_stat, g_q_stat);
    cudaGetSymbolAddress((void**)&q_tok,  g_q_tok);
    cudaGetSymbolAddress((void**)&k_stat, g_k_stat);

    const size_t WSZ = (size_t)512 * 512;
    constexpr int SMEM = 2 * (2 * 128 * 80 + 2 * 128 * 80);  // 81920
    constexpr int SMEM_WO = 4 * (32 * 80 + 2 * 64 * 80);     // 51200
    cudaFuncSetAttribute(gemm_batched, cudaFuncAttributeMaxDynamicSharedMemorySize, SMEM);
    cudaFuncSetAttribute(gemm_wo, cudaFuncAttributeMaxDynamicSharedMemorySize, SMEM_WO);
    cudaFuncSetAttribute(attn2, cudaFuncAttributeMaxDynamicSharedMemorySize, ATTN_SMEM);

    // 1) fused prep
    prep_all<<<10240, 256>>>(ws, queries, stat_keys, token_keys, values);

    // 2) all five projections in one launch (560 CTAs)
    GemmBatch gb;
    gb.Ah[0] = cq_h;  gb.Al[0] = cq_l;  gb.Bh[0] = wh;           gb.Bl[0] = wl;
    gb.C0[0] = q_stat; gb.C1[0] = q_tok; gb.Ho[0] = nullptr; gb.nbx[0] = 8; gb.cnt[0] = 32;
    gb.Ah[1] = csk_h; gb.Al[1] = csk_l; gb.Bh[1] = wh + 2 * WSZ; gb.Bl[1] = wl + 2 * WSZ;
    gb.C0[1] = k_stat; gb.C1[1] = nullptr; gb.Ho[1] = nullptr; gb.nbx[1] = 4; gb.cnt[1] = 16;
    gb.Ah[2] = ctk_h; gb.Al[2] = nullptr; gb.Bh[2] = wh + 3 * WSZ; gb.Bl[2] = nullptr;
    gb.C0[2] = nullptr; gb.C1[2] = nullptr; gb.Ho[2] = ktk16; gb.nbx[2] = 4; gb.cnt[2] = 256;
    gb.Ah[3] = cv_h;  gb.Al[3] = nullptr; gb.Bh[3] = wh + 4 * WSZ; gb.Bl[3] = nullptr;
    gb.C0[3] = nullptr; gb.C1[3] = nullptr; gb.Ho[3] = v16h; gb.nbx[3] = 4; gb.cnt[3] = 256;
    gemm_batched<<<560, 256, SMEM>>>(gb);

    // 3) attention v3
    attn2<<<dim3(64, 2), 512, ATTN_SMEM>>>(stat_valid_len);

    // 4) output projection: 128 CTAs of 32x64, 4-stage pipeline
    gemm_wo<<<dim3(8, 16), 128, SMEM_WO>>>(at_h, wh + 5 * WSZ, wl + 5 * WSZ, out);
}